// round 1
// baseline (speedup 1.0000x reference)
#include <cuda_runtime.h>

#define S_LEN  2048
#define DMODEL 1024
#define NHEAD  16
#define HDIM   64
#define MROWS  4096   // S*B
#define NPAIRS 32     // B*NHEAD

// Scratch (static device globals: allocation-free per harness rules)
__device__ float g_Q[(size_t)MROWS * DMODEL];
__device__ float g_K[(size_t)MROWS * DMODEL];
__device__ float g_V[(size_t)MROWS * DMODEL];
__device__ float g_Ctx[(size_t)MROWS * DMODEL];
__device__ float g_rowsum[NPAIRS * S_LEN];

// ---- packed f32x2 helpers (sm_103a FFMA2 path) ----
__device__ __forceinline__ unsigned long long pack2(float x) {
    unsigned long long d; unsigned u = __float_as_uint(x);
    asm("mov.b64 %0, {%1, %1};" : "=l"(d) : "r"(u));
    return d;
}
__device__ __forceinline__ unsigned long long fma2(unsigned long long a,
                                                   unsigned long long b,
                                                   unsigned long long c) {
    unsigned long long d;
    asm("fma.rn.f32x2 %0, %1, %2, %3;" : "=l"(d) : "l"(a), "l"(b), "l"(c));
    return d;
}
__device__ __forceinline__ float2 unpack2(unsigned long long v) {
    unsigned lo, hi;
    asm("mov.b64 {%0, %1}, %2;" : "=r"(lo), "=r"(hi) : "l"(v));
    return make_float2(__uint_as_float(lo), __uint_as_float(hi));
}

// ---------------------------------------------------------------------------
// Core 128x128 tile GEMM, K=1024:  C[r, c] = sum_k A[r,k] * W[c,k] + bias[c]
// (nn.Linear: y = x @ W^T + b; both operands K-contiguous)
// block = 256 threads (16x16), 8x8 outputs/thread, f32x2-packed accumulators.
// ---------------------------------------------------------------------------
__device__ __forceinline__ void gemm_core_1024(
    const float* __restrict__ A, const float* __restrict__ W,
    const float* __restrict__ bias, float* __restrict__ C)
{
    __shared__ float As[8][128];
    __shared__ float Ws[8][128];
    const int tid = threadIdx.x;
    const int tx = tid & 15, ty = tid >> 4;
    const int row0 = blockIdx.y * 128, col0 = blockIdx.x * 128;
    const int lrow = tid >> 1, lcol = (tid & 1) * 4;

    unsigned long long acc[8][4];
#pragma unroll
    for (int i = 0; i < 8; i++)
#pragma unroll
        for (int j = 0; j < 4; j++) acc[i][j] = 0ull;

    const float* Ap = A + (size_t)(row0 + lrow) * DMODEL + lcol;
    const float* Wp = W + (size_t)(col0 + lrow) * DMODEL + lcol;

    for (int k0 = 0; k0 < DMODEL; k0 += 8) {
        float4 a = *(const float4*)(Ap + k0);
        float4 w = *(const float4*)(Wp + k0);
        As[lcol + 0][lrow] = a.x; As[lcol + 1][lrow] = a.y;
        As[lcol + 2][lrow] = a.z; As[lcol + 3][lrow] = a.w;
        Ws[lcol + 0][lrow] = w.x; Ws[lcol + 1][lrow] = w.y;
        Ws[lcol + 2][lrow] = w.z; Ws[lcol + 3][lrow] = w.w;
        __syncthreads();
#pragma unroll
        for (int k = 0; k < 8; k++) {
            float4 a0 = *(const float4*)&As[k][ty * 8];
            float4 a1 = *(const float4*)&As[k][ty * 8 + 4];
            unsigned long long b0 = *(const unsigned long long*)&Ws[k][tx * 8];
            unsigned long long b1 = *(const unsigned long long*)&Ws[k][tx * 8 + 2];
            unsigned long long b2 = *(const unsigned long long*)&Ws[k][tx * 8 + 4];
            unsigned long long b3 = *(const unsigned long long*)&Ws[k][tx * 8 + 6];
            float ar[8] = {a0.x, a0.y, a0.z, a0.w, a1.x, a1.y, a1.z, a1.w};
#pragma unroll
            for (int i = 0; i < 8; i++) {
                unsigned long long a2 = pack2(ar[i]);
                acc[i][0] = fma2(a2, b0, acc[i][0]);
                acc[i][1] = fma2(a2, b1, acc[i][1]);
                acc[i][2] = fma2(a2, b2, acc[i][2]);
                acc[i][3] = fma2(a2, b3, acc[i][3]);
            }
        }
        __syncthreads();
    }

    const int c = col0 + tx * 8;
    float4 bia0 = *(const float4*)&bias[c];
    float4 bia1 = *(const float4*)&bias[c + 4];
#pragma unroll
    for (int i = 0; i < 8; i++) {
        const int r = row0 + ty * 8 + i;
        float2 u0 = unpack2(acc[i][0]);
        float2 u1 = unpack2(acc[i][1]);
        float2 u2 = unpack2(acc[i][2]);
        float2 u3 = unpack2(acc[i][3]);
        float4 o0 = make_float4(u0.x + bia0.x, u0.y + bia0.y, u1.x + bia0.z, u1.y + bia0.w);
        float4 o1 = make_float4(u2.x + bia1.x, u2.y + bia1.y, u3.x + bia1.z, u3.y + bia1.w);
        *(float4*)&C[(size_t)r * DMODEL + c]     = o0;
        *(float4*)&C[(size_t)r * DMODEL + c + 4] = o1;
    }
}

// QKV projections: blockIdx.z selects which of the three GEMMs.
__global__ void __launch_bounds__(256) qkv_proj(
    const float* __restrict__ q_in, const float* __restrict__ k_in, const float* __restrict__ v_in,
    const float* __restrict__ Wq, const float* __restrict__ Wk, const float* __restrict__ Wv,
    const float* __restrict__ bq, const float* __restrict__ bk, const float* __restrict__ bv)
{
    const int z = blockIdx.z;
    const float* A    = (z == 0) ? q_in : (z == 1) ? k_in : v_in;
    const float* W    = (z == 0) ? Wq   : (z == 1) ? Wk   : Wv;
    const float* bias = (z == 0) ? bq   : (z == 1) ? bk   : bv;
    float*       C    = (z == 0) ? g_Q  : (z == 1) ? g_K  : g_V;
    gemm_core_1024(A, W, bias, C);
}

// Output projection: out = Ctx @ Wo^T + bo  (rows map 1:1 to (S,B,D) flat)
__global__ void __launch_bounds__(256) out_proj(
    const float* __restrict__ Wo, const float* __restrict__ bo, float* __restrict__ C)
{
    gemm_core_1024(g_Ctx, Wo, bo, C);
}

__global__ void zero_rowsum_kernel() {
    int i = blockIdx.x * blockDim.x + threadIdx.x;
    if (i < NPAIRS * S_LEN) g_rowsum[i] = 0.f;
}

// ---------------------------------------------------------------------------
// QK^T per (b,h) pair: expS = exp(Q K^T / 8) written unnormalized to attn
// buffer; row sums accumulated into g_rowsum. M=N=2048, K=64 per pair.
// ---------------------------------------------------------------------------
__global__ void __launch_bounds__(256) qk_exp(float* __restrict__ attn)
{
    __shared__ float Qs[8][128];
    __shared__ float Ks[8][128];
    __shared__ float rsum[128];
    const int tid = threadIdx.x;
    const int tx = tid & 15, ty = tid >> 4;
    const int p = blockIdx.z, bb = p >> 4, h = p & 15;
    const int row0 = blockIdx.y * 128, col0 = blockIdx.x * 128;
    const int lrow = tid >> 1, lcol = (tid & 1) * 4;

    if (tid < 128) rsum[tid] = 0.f;

    unsigned long long acc[8][4];
#pragma unroll
    for (int i = 0; i < 8; i++)
#pragma unroll
        for (int j = 0; j < 4; j++) acc[i][j] = 0ull;

    const float* Qp = g_Q + (size_t)(bb * S_LEN + row0 + lrow) * DMODEL + h * HDIM + lcol;
    const float* Kp = g_K + (size_t)(bb * S_LEN + col0 + lrow) * DMODEL + h * HDIM + lcol;

#pragma unroll
    for (int k0 = 0; k0 < HDIM; k0 += 8) {
        float4 a = *(const float4*)(Qp + k0);
        float4 w = *(const float4*)(Kp + k0);
        Qs[lcol + 0][lrow] = a.x; Qs[lcol + 1][lrow] = a.y;
        Qs[lcol + 2][lrow] = a.z; Qs[lcol + 3][lrow] = a.w;
        Ks[lcol + 0][lrow] = w.x; Ks[lcol + 1][lrow] = w.y;
        Ks[lcol + 2][lrow] = w.z; Ks[lcol + 3][lrow] = w.w;
        __syncthreads();
#pragma unroll
        for (int k = 0; k < 8; k++) {
            float4 a0 = *(const float4*)&Qs[k][ty * 8];
            float4 a1 = *(const float4*)&Qs[k][ty * 8 + 4];
            unsigned long long b0 = *(const unsigned long long*)&Ks[k][tx * 8];
            unsigned long long b1 = *(const unsigned long long*)&Ks[k][tx * 8 + 2];
            unsigned long long b2 = *(const unsigned long long*)&Ks[k][tx * 8 + 4];
            unsigned long long b3 = *(const unsigned long long*)&Ks[k][tx * 8 + 6];
            float ar[8] = {a0.x, a0.y, a0.z, a0.w, a1.x, a1.y, a1.z, a1.w};
#pragma unroll
            for (int i = 0; i < 8; i++) {
                unsigned long long a2 = pack2(ar[i]);
                acc[i][0] = fma2(a2, b0, acc[i][0]);
                acc[i][1] = fma2(a2, b1, acc[i][1]);
                acc[i][2] = fma2(a2, b2, acc[i][2]);
                acc[i][3] = fma2(a2, b3, acc[i][3]);
            }
        }
        __syncthreads();
    }

    // epilogue: scale by 1/sqrt(hd)=1/8, exp (softmax is shift-invariant;
    // scores are O(1) so no max-subtraction is needed in fp32), store,
    // accumulate row sums.
    const float sc = 0.125f;
#pragma unroll
    for (int i = 0; i < 8; i++) {
        float e[8];
        float2 u0 = unpack2(acc[i][0]);
        float2 u1 = unpack2(acc[i][1]);
        float2 u2 = unpack2(acc[i][2]);
        float2 u3 = unpack2(acc[i][3]);
        e[0] = __expf(u0.x * sc); e[1] = __expf(u0.y * sc);
        e[2] = __expf(u1.x * sc); e[3] = __expf(u1.y * sc);
        e[4] = __expf(u2.x * sc); e[5] = __expf(u2.y * sc);
        e[6] = __expf(u3.x * sc); e[7] = __expf(u3.y * sc);
        float rp = ((e[0] + e[1]) + (e[2] + e[3])) + ((e[4] + e[5]) + (e[6] + e[7]));
        atomicAdd(&rsum[ty * 8 + i], rp);
        const size_t gbase = ((size_t)(p * S_LEN + row0 + ty * 8 + i)) * S_LEN + col0 + tx * 8;
        *(float4*)&attn[gbase]     = make_float4(e[0], e[1], e[2], e[3]);
        *(float4*)&attn[gbase + 4] = make_float4(e[4], e[5], e[6], e[7]);
    }
    __syncthreads();
    if (tid < 128)
        atomicAdd(&g_rowsum[p * S_LEN + row0 + tid], rsum[tid]);
}

// ---------------------------------------------------------------------------
// Fused normalize + PV: reads unnormalized expS, writes normalized attn back
// in-place, and computes Ctx = attn @ V per (b,h) pair (2048 x 64 x 2048).
// ---------------------------------------------------------------------------
__global__ void __launch_bounds__(256) pv_norm(float* __restrict__ attn)
{
    __shared__ float Ss[128][32];   // [row][t] — A-reads are ty-broadcast (conflict-free)
    __shared__ float Vs[32][64];
    __shared__ float sinv[128];
    const int tid = threadIdx.x;
    const int tx = tid & 15, ty = tid >> 4;
    const int p = blockIdx.y, bb = p >> 4, h = p & 15;
    const int row0 = blockIdx.x * 128;

    if (tid < 128) sinv[tid] = 1.0f / g_rowsum[p * S_LEN + row0 + tid];
    __syncthreads();

    unsigned long long acc[8][2];
#pragma unroll
    for (int i = 0; i < 8; i++) { acc[i][0] = 0ull; acc[i][1] = 0ull; }

    for (int t0 = 0; t0 < S_LEN; t0 += 32) {
#pragma unroll
        for (int ps = 0; ps < 4; ps++) {
            const int f = tid + ps * 256;          // 0..1023
            const int r = f >> 3;                  // 0..127
            const int c4 = (f & 7) * 4;            // 0..28
            const size_t g = ((size_t)(p * S_LEN + row0 + r)) * S_LEN + t0 + c4;
            float4 v = *(const float4*)(attn + g);
            const float inv = sinv[r];
            v.x *= inv; v.y *= inv; v.z *= inv; v.w *= inv;
            *(float4*)(attn + g) = v;              // final normalized attn output
            *(float4*)&Ss[r][c4] = v;
        }
#pragma unroll
        for (int ps = 0; ps < 2; ps++) {
            const int f = tid + ps * 256;          // 0..511
            const int k = f >> 4, e4 = (f & 15) * 4;
            *(float4*)&Vs[k][e4] =
                *(const float4*)(g_V + (size_t)(bb * S_LEN + t0 + k) * DMODEL + h * HDIM + e4);
        }
        __syncthreads();
#pragma unroll
        for (int k = 0; k < 32; k++) {
            unsigned long long v0 = *(const unsigned long long*)&Vs[k][tx * 4];
            unsigned long long v1 = *(const unsigned long long*)&Vs[k][tx * 4 + 2];
#pragma unroll
            for (int i = 0; i < 8; i++) {
                unsigned long long a2 = pack2(Ss[ty * 8 + i][k]);
                acc[i][0] = fma2(a2, v0, acc[i][0]);
                acc[i][1] = fma2(a2, v1, acc[i][1]);
            }
        }
        __syncthreads();
    }

#pragma unroll
    for (int i = 0; i < 8; i++) {
        float2 u0 = unpack2(acc[i][0]);
        float2 u1 = unpack2(acc[i][1]);
        *(float4*)&g_Ctx[(size_t)(bb * S_LEN + row0 + ty * 8 + i) * DMODEL + h * HDIM + tx * 4]
            = make_float4(u0.x, u0.y, u1.x, u1.y);
    }
}

extern "C" void kernel_launch(void* const* d_in, const int* in_sizes, int n_in,
                              void* d_out, int out_size) {
    const float* query = (const float*)d_in[0];
    const float* key_  = (const float*)d_in[1];
    const float* value = (const float*)d_in[2];
    const float* Wq = (const float*)d_in[3];
    const float* bq = (const float*)d_in[4];
    const float* Wk = (const float*)d_in[5];
    const float* bk = (const float*)d_in[6];
    const float* Wv = (const float*)d_in[7];
    const float* bv = (const float*)d_in[8];
    const float* Wo = (const float*)d_in[9];
    const float* bo = (const float*)d_in[10];

    float* outp = (float*)d_out;
    float* attn = outp + (size_t)MROWS * DMODEL;   // tuple output: (out, attn)

    zero_rowsum_kernel<<<NPAIRS * S_LEN / 256, 256>>>();
    qkv_proj<<<dim3(DMODEL / 128, MROWS / 128, 3), 256>>>(
        query, key_, value, Wq, Wk, Wv, bq, bk, bv);
    qk_exp<<<dim3(S_LEN / 128, S_LEN / 128, NPAIRS), 256>>>(attn);
    pv_norm<<<dim3(S_LEN / 128, NPAIRS), 256>>>(attn);
    out_proj<<<dim3(DMODEL / 128, MROWS / 128), 256>>>(Wo, bo, outp);
}

// round 2
// speedup vs baseline: 1.2444x; 1.2444x over previous
#include <cuda_runtime.h>

#define S_LEN  2048
#define DMODEL 1024
#define NHEAD  16
#define HDIM   64
#define MROWS  4096   // S*B
#define NPAIRS 32     // B*NHEAD

// Scratch (static device globals: allocation-free per harness rules)
__device__ float g_Q[(size_t)MROWS * DMODEL];
__device__ float g_K[(size_t)MROWS * DMODEL];
__device__ float g_V[(size_t)MROWS * DMODEL];
__device__ float g_Ctx[(size_t)MROWS * DMODEL];
__device__ float g_rowinv[NPAIRS * S_LEN];   // 1/rowsum per attn row

typedef unsigned long long u64;

// ---- packed f32x2 helpers (sm_103a FFMA2 path) ----
__device__ __forceinline__ u64 pack2(float x) {
    u64 d; unsigned u = __float_as_uint(x);
    asm("mov.b64 %0, {%1, %1};" : "=l"(d) : "r"(u));
    return d;
}
__device__ __forceinline__ u64 fma2(u64 a, u64 b, u64 c) {
    u64 d;
    asm("fma.rn.f32x2 %0, %1, %2, %3;" : "=l"(d) : "l"(a), "l"(b), "l"(c));
    return d;
}
__device__ __forceinline__ float2 unpack2(u64 v) {
    unsigned lo, hi;
    asm("mov.b64 {%0, %1}, %2;" : "=r"(lo), "=r"(hi) : "l"(v));
    return make_float2(__uint_as_float(lo), __uint_as_float(hi));
}

// ---------------------------------------------------------------------------
// 128x128 tile GEMM, K=1024, double-buffered smem, 1 sync per 8-k chunk.
// C[r, c] = sum_k A[r,k] * W[c,k] + bias[c]
// ---------------------------------------------------------------------------
__device__ __forceinline__ void gemm_core_1024(
    const float* __restrict__ A, const float* __restrict__ W,
    const float* __restrict__ bias, float* __restrict__ C)
{
    __shared__ float As[2][8][128];
    __shared__ float Ws[2][8][128];
    const int tid = threadIdx.x;
    const int tx = tid & 15, ty = tid >> 4;
    const int row0 = blockIdx.y * 128, col0 = blockIdx.x * 128;
    const int lrow = tid >> 1, lcol = (tid & 1) * 4;

    u64 acc[8][4];
#pragma unroll
    for (int i = 0; i < 8; i++)
#pragma unroll
        for (int j = 0; j < 4; j++) acc[i][j] = 0ull;

    const float* Ap = A + (size_t)(row0 + lrow) * DMODEL + lcol;
    const float* Wp = W + (size_t)(col0 + lrow) * DMODEL + lcol;

    float4 a = *(const float4*)Ap;
    float4 w = *(const float4*)Wp;
    int buf = 0;

    for (int k0 = 0; k0 < DMODEL; k0 += 8) {
        As[buf][lcol + 0][lrow] = a.x; As[buf][lcol + 1][lrow] = a.y;
        As[buf][lcol + 2][lrow] = a.z; As[buf][lcol + 3][lrow] = a.w;
        Ws[buf][lcol + 0][lrow] = w.x; Ws[buf][lcol + 1][lrow] = w.y;
        Ws[buf][lcol + 2][lrow] = w.z; Ws[buf][lcol + 3][lrow] = w.w;
        __syncthreads();
        if (k0 + 8 < DMODEL) {
            a = *(const float4*)(Ap + k0 + 8);
            w = *(const float4*)(Wp + k0 + 8);
        }
#pragma unroll
        for (int k = 0; k < 8; k++) {
            float4 a0 = *(const float4*)&As[buf][k][ty * 8];
            float4 a1 = *(const float4*)&As[buf][k][ty * 8 + 4];
            u64 b0 = *(const u64*)&Ws[buf][k][tx * 8];
            u64 b1 = *(const u64*)&Ws[buf][k][tx * 8 + 2];
            u64 b2 = *(const u64*)&Ws[buf][k][tx * 8 + 4];
            u64 b3 = *(const u64*)&Ws[buf][k][tx * 8 + 6];
            float ar[8] = {a0.x, a0.y, a0.z, a0.w, a1.x, a1.y, a1.z, a1.w};
#pragma unroll
            for (int i = 0; i < 8; i++) {
                u64 a2 = pack2(ar[i]);
                acc[i][0] = fma2(a2, b0, acc[i][0]);
                acc[i][1] = fma2(a2, b1, acc[i][1]);
                acc[i][2] = fma2(a2, b2, acc[i][2]);
                acc[i][3] = fma2(a2, b3, acc[i][3]);
            }
        }
        buf ^= 1;
    }

    const int c = col0 + tx * 8;
    float4 bia0 = *(const float4*)&bias[c];
    float4 bia1 = *(const float4*)&bias[c + 4];
#pragma unroll
    for (int i = 0; i < 8; i++) {
        const int r = row0 + ty * 8 + i;
        float2 u0 = unpack2(acc[i][0]);
        float2 u1 = unpack2(acc[i][1]);
        float2 u2 = unpack2(acc[i][2]);
        float2 u3 = unpack2(acc[i][3]);
        float4 o0 = make_float4(u0.x + bia0.x, u0.y + bia0.y, u1.x + bia0.z, u1.y + bia0.w);
        float4 o1 = make_float4(u2.x + bia1.x, u2.y + bia1.y, u3.x + bia1.z, u3.y + bia1.w);
        *(float4*)&C[(size_t)r * DMODEL + c]     = o0;
        *(float4*)&C[(size_t)r * DMODEL + c + 4] = o1;
    }
}

__global__ void __launch_bounds__(256, 2) qkv_proj(
    const float* __restrict__ q_in, const float* __restrict__ k_in, const float* __restrict__ v_in,
    const float* __restrict__ Wq, const float* __restrict__ Wk, const float* __restrict__ Wv,
    const float* __restrict__ bq, const float* __restrict__ bk, const float* __restrict__ bv)
{
    const int z = blockIdx.z;
    const float* A    = (z == 0) ? q_in : (z == 1) ? k_in : v_in;
    const float* W    = (z == 0) ? Wq   : (z == 1) ? Wk   : Wv;
    const float* bias = (z == 0) ? bq   : (z == 1) ? bk   : bv;
    float*       C    = (z == 0) ? g_Q  : (z == 1) ? g_K  : g_V;
    gemm_core_1024(A, W, bias, C);
}

__global__ void __launch_bounds__(256, 2) out_proj(
    const float* __restrict__ Wo, const float* __restrict__ bo, float* __restrict__ C)
{
    gemm_core_1024(g_Ctx, Wo, bo, C);
}

// ---------------------------------------------------------------------------
// Fused flash-style attention: per (pair, 128-row tile) iterate over 64-col
// chunks of K/V. Computes S = QK^T/8, expS (written unnormalized to attn),
// accumulates rowsum + PV, scales context by 1/rowsum at the end.
// Dynamic smem layout (floats):
//   Qs [128][68]           8704
//   Kt [64 k][64 seq]      4096   (k-major, XOR-swizzled seq for conflict-free
//                                  transpose stores: word = k*64 + (seq ^ (((k>>4)&3)<<3)))
//   Vs [64 seq][76]        4864
//   Ss [128][68]           8704
// total 26368 floats = 105472 B  (2 blocks/SM)
// ---------------------------------------------------------------------------
#define QS_OFF 0
#define KT_OFF 8704
#define VS_OFF (8704 + 4096)
#define SS_OFF (8704 + 4096 + 4864)
#define QKPV_SMEM_FLOATS (8704 + 4096 + 4864 + 8704)

__global__ void __launch_bounds__(256, 2) qk_pv(float* __restrict__ attn)
{
    extern __shared__ float sm[];
    float* Qs = sm + QS_OFF;
    float* Kt = sm + KT_OFF;
    float* Vs = sm + VS_OFF;
    float* Ss = sm + SS_OFF;

    const int tid = threadIdx.x;
    const int tx = tid & 15, ty = tid >> 4;
    const int p = blockIdx.y, bb = p >> 4, h = p & 15;
    const int row0 = blockIdx.x * 128;

    // --- load Q tile (128 x 64) ---
    {
        const int lrow = tid >> 1, lc = (tid & 1) * 4;
        const float* Qp = g_Q + (size_t)(bb * S_LEN + row0 + lrow) * DMODEL + h * HDIM;
#pragma unroll
        for (int c0 = 0; c0 < HDIM; c0 += 8)
            *(float4*)&Qs[lrow * 68 + c0 + lc] = *(const float4*)(Qp + c0 + lc);
    }

    u64 accPV[8][2];
    float rs[8];
#pragma unroll
    for (int i = 0; i < 8; i++) { accPV[i][0] = 0ull; accPV[i][1] = 0ull; rs[i] = 0.f; }

    const int krow = tid >> 2;            // 0..63 (seq within chunk)
    const int kc   = (tid & 3) * 16;      // 16-wide k/hd segment
    const int swz_t = (tid & 3) << 3;     // Kt store swizzle for this thread
    const float* Kbase = g_K + (size_t)(bb * S_LEN + krow) * DMODEL + h * HDIM + kc;
    const float* Vbase = g_V + (size_t)(bb * S_LEN + krow) * DMODEL + h * HDIM + kc;

    for (int c0 = 0; c0 < S_LEN; c0 += 64) {
        // --- load K (transposed+swizzled) and V chunk ---
#pragma unroll
        for (int j = 0; j < 4; j++) {
            float4 kv = *(const float4*)(Kbase + (size_t)c0 * DMODEL + j * 4);
            const int e = kc + j * 4;
            Kt[(e + 0) * 64 + (krow ^ swz_t)] = kv.x;
            Kt[(e + 1) * 64 + (krow ^ swz_t)] = kv.y;
            Kt[(e + 2) * 64 + (krow ^ swz_t)] = kv.z;
            Kt[(e + 3) * 64 + (krow ^ swz_t)] = kv.w;
            *(float4*)&Vs[krow * 76 + e] = *(const float4*)(Vbase + (size_t)c0 * DMODEL + j * 4);
        }
        __syncthreads();

        // --- S = Q K^T : this thread rows ty*8..+7, cols tx*4..+3 ---
        u64 accS[8][2];
#pragma unroll
        for (int i = 0; i < 8; i++) { accS[i][0] = 0ull; accS[i][1] = 0ull; }
#pragma unroll
        for (int k = 0; k < HDIM; k += 2) {
            const int cw = (4 * tx) ^ (((k >> 4) & 3) << 3);
            u64 b00 = *(const u64*)&Kt[k * 64 + cw];
            u64 b01 = *(const u64*)&Kt[k * 64 + cw + 2];
            u64 b10 = *(const u64*)&Kt[(k + 1) * 64 + cw];
            u64 b11 = *(const u64*)&Kt[(k + 1) * 64 + cw + 2];
#pragma unroll
            for (int i = 0; i < 8; i++) {
                float2 aa = *(const float2*)&Qs[(ty * 8 + i) * 68 + k];
                u64 a0 = pack2(aa.x), a1 = pack2(aa.y);
                accS[i][0] = fma2(a0, b00, accS[i][0]);
                accS[i][1] = fma2(a0, b01, accS[i][1]);
                accS[i][0] = fma2(a1, b10, accS[i][0]);
                accS[i][1] = fma2(a1, b11, accS[i][1]);
            }
        }

        // --- exp, stage to smem + gmem, accumulate rowsum ---
        const float sc = 0.125f;
#pragma unroll
        for (int i = 0; i < 8; i++) {
            float2 u0 = unpack2(accS[i][0]);
            float2 u1 = unpack2(accS[i][1]);
            float e0 = __expf(u0.x * sc), e1 = __expf(u0.y * sc);
            float e2 = __expf(u1.x * sc), e3 = __expf(u1.y * sc);
            rs[i] += (e0 + e1) + (e2 + e3);
            const int row = ty * 8 + i;
            float4 ev = make_float4(e0, e1, e2, e3);
            *(float4*)&Ss[row * 68 + tx * 4] = ev;
            *(float4*)&attn[((size_t)(p * S_LEN + row0 + row)) * S_LEN + c0 + tx * 4] = ev;
        }
        __syncthreads();

        // --- PV: Ctx(128x64) += Ss(128x64) * Vs(64x64) ---
#pragma unroll
        for (int k = 0; k < 64; k += 2) {
            u64 v00 = *(const u64*)&Vs[k * 76 + tx * 4];
            u64 v01 = *(const u64*)&Vs[k * 76 + tx * 4 + 2];
            u64 v10 = *(const u64*)&Vs[(k + 1) * 76 + tx * 4];
            u64 v11 = *(const u64*)&Vs[(k + 1) * 76 + tx * 4 + 2];
#pragma unroll
            for (int i = 0; i < 8; i++) {
                float2 ss = *(const float2*)&Ss[(ty * 8 + i) * 68 + k];
                u64 a0 = pack2(ss.x), a1 = pack2(ss.y);
                accPV[i][0] = fma2(a0, v00, accPV[i][0]);
                accPV[i][1] = fma2(a0, v01, accPV[i][1]);
                accPV[i][0] = fma2(a1, v10, accPV[i][0]);
                accPV[i][1] = fma2(a1, v11, accPV[i][1]);
            }
        }
        __syncthreads();
    }

    // --- rowsum reduce across the 16 tx lanes (within half-warp) ---
#pragma unroll
    for (int i = 0; i < 8; i++) {
        float v = rs[i];
        v += __shfl_xor_sync(0xffffffffu, v, 8);
        v += __shfl_xor_sync(0xffffffffu, v, 4);
        v += __shfl_xor_sync(0xffffffffu, v, 2);
        v += __shfl_xor_sync(0xffffffffu, v, 1);
        rs[i] = v;
    }

    // --- write row inverses + scaled context ---
#pragma unroll
    for (int i = 0; i < 8; i++) {
        const int row = ty * 8 + i;
        const float inv = 1.0f / rs[i];
        if (tx == 0) g_rowinv[p * S_LEN + row0 + row] = inv;
        float2 u0 = unpack2(accPV[i][0]);
        float2 u1 = unpack2(accPV[i][1]);
        float4 o = make_float4(u0.x * inv, u0.y * inv, u1.x * inv, u1.y * inv);
        *(float4*)&g_Ctx[(size_t)(bb * S_LEN + row0 + row) * DMODEL + h * HDIM + tx * 4] = o;
    }
}

// ---------------------------------------------------------------------------
// Streaming normalize of attn: one float4 per thread.
// ---------------------------------------------------------------------------
__global__ void __launch_bounds__(256) norm_attn(float* __restrict__ attn)
{
    const size_t i = (size_t)blockIdx.x * 256 + threadIdx.x;   // float4 index
    const size_t r = i >> 9;                                    // 512 float4 per row
    const float inv = g_rowinv[r];
    float4 v = ((const float4*)attn)[i];
    v.x *= inv; v.y *= inv; v.z *= inv; v.w *= inv;
    ((float4*)attn)[i] = v;
}

extern "C" void kernel_launch(void* const* d_in, const int* in_sizes, int n_in,
                              void* d_out, int out_size) {
    const float* query = (const float*)d_in[0];
    const float* key_  = (const float*)d_in[1];
    const float* value = (const float*)d_in[2];
    const float* Wq = (const float*)d_in[3];
    const float* bq = (const float*)d_in[4];
    const float* Wk = (const float*)d_in[5];
    const float* bk = (const float*)d_in[6];
    const float* Wv = (const float*)d_in[7];
    const float* bv = (const float*)d_in[8];
    const float* Wo = (const float*)d_in[9];
    const float* bo = (const float*)d_in[10];

    float* outp = (float*)d_out;
    float* attn = outp + (size_t)MROWS * DMODEL;   // tuple output: (out, attn)

    static int smem_set = 0;
    if (!smem_set) {
        cudaFuncSetAttribute(qk_pv, cudaFuncAttributeMaxDynamicSharedMemorySize,
                             QKPV_SMEM_FLOATS * (int)sizeof(float));
        smem_set = 1;
    }

    qkv_proj<<<dim3(DMODEL / 128, MROWS / 128, 3), 256>>>(
        query, key_, value, Wq, Wk, Wv, bq, bk, bv);
    qk_pv<<<dim3(S_LEN / 128, NPAIRS), 256, QKPV_SMEM_FLOATS * sizeof(float)>>>(attn);
    norm_attn<<<(NPAIRS * (size_t)S_LEN * S_LEN / 4) / 256, 256>>>(attn);
    out_proj<<<dim3(DMODEL / 128, MROWS / 128), 256>>>(Wo, bo, outp);
}

// round 5
// speedup vs baseline: 1.7394x; 1.3978x over previous
#include <cuda_runtime.h>
#include <cuda_bf16.h>
#include <cstdint>

#define S_LEN  2048
#define DMODEL 1024
#define NHEAD  16
#define HDIM   64
#define MROWS  4096   // S*B
#define NPAIRS 32     // B*NHEAD

typedef unsigned long long u64;

// ---------------- scratch globals (allocation-free rule) ----------------
__device__ float g_Q[(size_t)MROWS * DMODEL];
__device__ float g_K[(size_t)MROWS * DMODEL];
__device__ float g_V[(size_t)MROWS * DMODEL];
__device__ float g_rowinv[NPAIRS * S_LEN];

__device__ __nv_bfloat16 g_hiX[(size_t)3 * MROWS * DMODEL];  // converted q/k/v inputs
__device__ __nv_bfloat16 g_loX[(size_t)3 * MROWS * DMODEL];
__device__ __nv_bfloat16 g_hiW[(size_t)4 * DMODEL * DMODEL]; // converted Wq,Wk,Wv,Wo
__device__ __nv_bfloat16 g_loW[(size_t)4 * DMODEL * DMODEL];
__device__ __nv_bfloat16 g_hiC[(size_t)MROWS * DMODEL];      // attention context hi/lo
__device__ __nv_bfloat16 g_loC[(size_t)MROWS * DMODEL];

// ---------------- helpers ----------------
__device__ __forceinline__ uint32_t smem_u32(const void* p) {
    uint32_t a;
    asm("{ .reg .u64 t; cvta.to.shared.u64 t, %1; cvt.u32.u64 %0, t; }" : "=r"(a) : "l"(p));
    return a;
}
__device__ __forceinline__ void ldsm4(uint32_t* r, uint32_t a) {
    asm volatile("ldmatrix.sync.aligned.m8n8.x4.shared.b16 {%0,%1,%2,%3}, [%4];"
        : "=r"(r[0]), "=r"(r[1]), "=r"(r[2]), "=r"(r[3]) : "r"(a));
}
__device__ __forceinline__ void mma_bf16(float* d, const uint32_t* a, const uint32_t* b) {
    asm volatile("mma.sync.aligned.m16n8k16.row.col.f32.bf16.bf16.f32 "
        "{%0,%1,%2,%3},{%4,%5,%6,%7},{%8,%9},{%0,%1,%2,%3};"
        : "+f"(d[0]), "+f"(d[1]), "+f"(d[2]), "+f"(d[3])
        : "r"(a[0]), "r"(a[1]), "r"(a[2]), "r"(a[3]), "r"(b[0]), "r"(b[1]));
}
// Swizzled smem byte offset for a (row, 16B-chunk) pair.
#define SWB(row, ch) (((row) << 6) + ((((ch) ^ (((row) >> 1) & 3))) << 4))

// ---------------- fp32 -> bf16 hi/lo split conversion ----------------
__global__ void __launch_bounds__(256) conv_split(
    const float* __restrict__ src, __nv_bfloat16* __restrict__ hi,
    __nv_bfloat16* __restrict__ lo)
{
    const size_t i = ((size_t)blockIdx.x * 256 + threadIdx.x) * 4;
    float4 v = *(const float4*)(src + i);
    __nv_bfloat16 h0 = __float2bfloat16(v.x), h1 = __float2bfloat16(v.y);
    __nv_bfloat16 h2 = __float2bfloat16(v.z), h3 = __float2bfloat16(v.w);
    *(__nv_bfloat162*)(hi + i)     = __nv_bfloat162(h0, h1);
    *(__nv_bfloat162*)(hi + i + 2) = __nv_bfloat162(h2, h3);
    *(__nv_bfloat162*)(lo + i)     = __nv_bfloat162(
        __float2bfloat16(v.x - __bfloat162float(h0)),
        __float2bfloat16(v.y - __bfloat162float(h1)));
    *(__nv_bfloat162*)(lo + i + 2) = __nv_bfloat162(
        __float2bfloat16(v.z - __bfloat162float(h2)),
        __float2bfloat16(v.w - __bfloat162float(h3)));
}

// ---------------------------------------------------------------------------
// mma.sync bf16x3 GEMM: C[128 rows x 64 cols per block] = A * W^T + bias
// A: (M x 1024) hi/lo bf16 K-major; W: (N x 1024) hi/lo bf16 K-major.
// 256 threads = 8 warps (4 m-warps x 2 n-warps), warp tile 32x32.
// Both A and W tiles are K-contiguous => NON-trans ldmatrix yields the
// correct row.col fragments for mma.m16n8k16 (A: m=l/4; B: n=l/4).
// ---------------------------------------------------------------------------
__device__ __forceinline__ void gemm_mma_core(
    const __nv_bfloat16* __restrict__ Ahi, const __nv_bfloat16* __restrict__ Alo,
    const __nv_bfloat16* __restrict__ Whi, const __nv_bfloat16* __restrict__ Wlo,
    const float* __restrict__ bias, float* __restrict__ C)
{
    __shared__ char smbuf[49152];   // 2 x 24576
    const int tid = threadIdx.x, lane = tid & 31, wid = tid >> 5;
    const int warpM = wid & 3, warpN = wid >> 2;
    const int row0 = blockIdx.y * 128, col0 = blockIdx.x * 64;
    const uint32_t sb = smem_u32(smbuf);

    // global load mapping: 6 x 16B per thread per 32-K chunk
    const int grow = tid >> 2, gch = tid & 3;
    const size_t aoff0 = (size_t)(row0 + grow) * (DMODEL * 2) + gch * 16;
    const size_t aoff1 = aoff0 + (size_t)64 * (DMODEL * 2);
    const size_t woff  = (size_t)(col0 + grow) * (DMODEL * 2) + gch * 16;
    const uint32_t dA0 = SWB(grow, gch);
    const uint32_t dA1 = SWB(grow + 64, gch);
    const uint32_t dW  = SWB(grow, gch);

    float acc[2][4][4];
#pragma unroll
    for (int mt = 0; mt < 2; mt++)
#pragma unroll
        for (int nt = 0; nt < 4; nt++)
#pragma unroll
            for (int e = 0; e < 4; e++) acc[mt][nt][e] = 0.f;

    uint4 pre[6];
    {
        pre[0] = *(const uint4*)((const char*)Ahi + aoff0);
        pre[1] = *(const uint4*)((const char*)Ahi + aoff1);
        pre[2] = *(const uint4*)((const char*)Alo + aoff0);
        pre[3] = *(const uint4*)((const char*)Alo + aoff1);
        pre[4] = *(const uint4*)((const char*)Whi + woff);
        pre[5] = *(const uint4*)((const char*)Wlo + woff);
    }

    // ldmatrix lane addressing (local rows/chunks)
    const int arowl = warpM * 32 + (lane & 7) + ((lane >> 3) & 1) * 8;
    const int achl  = (lane >> 4) & 1;
    const int browl = warpN * 32 + (lane & 7) + ((lane >> 4) & 1) * 8;
    const int bchl  = (lane >> 3) & 1;

    int buf = 0;
    for (int c = 0; c < 32; c++) {
        char* base = smbuf + buf * 24576;
        *(uint4*)(base + 0     + dA0) = pre[0];
        *(uint4*)(base + 0     + dA1) = pre[1];
        *(uint4*)(base + 8192  + dA0) = pre[2];
        *(uint4*)(base + 8192  + dA1) = pre[3];
        *(uint4*)(base + 16384 + dW)  = pre[4];
        *(uint4*)(base + 20480 + dW)  = pre[5];
        __syncthreads();

        if (c + 1 < 32) {
            const size_t cb = (size_t)(c + 1) * 64;
            pre[0] = *(const uint4*)((const char*)Ahi + aoff0 + cb);
            pre[1] = *(const uint4*)((const char*)Ahi + aoff1 + cb);
            pre[2] = *(const uint4*)((const char*)Alo + aoff0 + cb);
            pre[3] = *(const uint4*)((const char*)Alo + aoff1 + cb);
            pre[4] = *(const uint4*)((const char*)Whi + woff + cb);
            pre[5] = *(const uint4*)((const char*)Wlo + woff + cb);
        }

        const uint32_t bb = sb + buf * 24576;
#pragma unroll
        for (int ks = 0; ks < 2; ks++) {
            uint32_t a_hi[2][4], a_lo[2][4], b_hi[2][4], b_lo[2][4];
#pragma unroll
            for (int mt = 0; mt < 2; mt++) {
                const uint32_t ao = SWB(arowl + mt * 16, ks * 2 + achl);
                ldsm4(a_hi[mt], bb + 0    + ao);
                ldsm4(a_lo[mt], bb + 8192 + ao);
            }
#pragma unroll
            for (int np = 0; np < 2; np++) {
                const uint32_t bo = SWB(browl + np * 16, ks * 2 + bchl);
                ldsm4(b_hi[np], bb + 16384 + bo);   // non-trans: [n][k] tile
                ldsm4(b_lo[np], bb + 20480 + bo);
            }
#pragma unroll
            for (int mt = 0; mt < 2; mt++)
#pragma unroll
                for (int nt = 0; nt < 4; nt++) {
                    const uint32_t* bh = &b_hi[nt >> 1][(nt & 1) * 2];
                    const uint32_t* bl = &b_lo[nt >> 1][(nt & 1) * 2];
                    mma_bf16(acc[mt][nt], a_hi[mt], bh);
                    mma_bf16(acc[mt][nt], a_hi[mt], bl);
                    mma_bf16(acc[mt][nt], a_lo[mt], bh);
                }
        }
        buf ^= 1;
    }

    // epilogue
#pragma unroll
    for (int mt = 0; mt < 2; mt++) {
        const int r = row0 + warpM * 32 + mt * 16 + (lane >> 2);
#pragma unroll
        for (int nt = 0; nt < 4; nt++) {
            const int col = col0 + warpN * 32 + nt * 8 + (lane & 3) * 2;
            const float b0 = bias[col], b1 = bias[col + 1];
            float2 o0 = make_float2(acc[mt][nt][0] + b0, acc[mt][nt][1] + b1);
            float2 o1 = make_float2(acc[mt][nt][2] + b0, acc[mt][nt][3] + b1);
            *(float2*)&C[(size_t)r * DMODEL + col]       = o0;
            *(float2*)&C[(size_t)(r + 8) * DMODEL + col] = o1;
        }
    }
}

__global__ void __launch_bounds__(256, 2) qkv_mma(
    const float* __restrict__ bq, const float* __restrict__ bk, const float* __restrict__ bv)
{
    const int z = blockIdx.z;
    const size_t xo = (size_t)z * MROWS * DMODEL;
    const size_t wo = (size_t)z * DMODEL * DMODEL;
    const float* bias = (z == 0) ? bq : (z == 1) ? bk : bv;
    float* C = (z == 0) ? g_Q : (z == 1) ? g_K : g_V;
    gemm_mma_core(g_hiX + xo, g_loX + xo, g_hiW + wo, g_loW + wo, bias, C);
}

__global__ void __launch_bounds__(256, 2) out_mma(
    const float* __restrict__ bo, float* __restrict__ C)
{
    gemm_mma_core(g_hiC, g_loC, g_hiW + (size_t)3 * DMODEL * DMODEL,
                  g_loW + (size_t)3 * DMODEL * DMODEL, bo, C);
}

// ---- packed f32x2 helpers (sm_103a FFMA2 path) ----
__device__ __forceinline__ u64 pack2(float x) {
    u64 d; unsigned u = __float_as_uint(x);
    asm("mov.b64 %0, {%1, %1};" : "=l"(d) : "r"(u));
    return d;
}
__device__ __forceinline__ u64 fma2(u64 a, u64 b, u64 c) {
    u64 d;
    asm("fma.rn.f32x2 %0, %1, %2, %3;" : "=l"(d) : "l"(a), "l"(b), "l"(c));
    return d;
}
__device__ __forceinline__ float2 unpack2(u64 v) {
    unsigned lo, hi;
    asm("mov.b64 {%0, %1}, %2;" : "=r"(lo), "=r"(hi) : "l"(v));
    return make_float2(__uint_as_float(lo), __uint_as_float(hi));
}

// ---------------------------------------------------------------------------
// Fused flash-style attention (SIMT fp32, passing since R2). Ctx -> bf16 hi/lo.
// ---------------------------------------------------------------------------
#define QS_OFF 0
#define KT_OFF 8704
#define VS_OFF (8704 + 4096)
#define SS_OFF (8704 + 4096 + 4864)
#define QKPV_SMEM_FLOATS (8704 + 4096 + 4864 + 8704)

__global__ void __launch_bounds__(256, 2) qk_pv(float* __restrict__ attn)
{
    extern __shared__ float smf[];
    float* Qs = smf + QS_OFF;
    float* Kt = smf + KT_OFF;
    float* Vs = smf + VS_OFF;
    float* Ss = smf + SS_OFF;

    const int tid = threadIdx.x;
    const int tx = tid & 15, ty = tid >> 4;
    const int p = blockIdx.y, bb = p >> 4, h = p & 15;
    const int row0 = blockIdx.x * 128;

    {
        const int lrow = tid >> 1, lc = (tid & 1) * 4;
        const float* Qp = g_Q + (size_t)(bb * S_LEN + row0 + lrow) * DMODEL + h * HDIM;
#pragma unroll
        for (int c0 = 0; c0 < HDIM; c0 += 8)
            *(float4*)&Qs[lrow * 68 + c0 + lc] = *(const float4*)(Qp + c0 + lc);
    }

    u64 accPV[8][2];
    float rs[8];
#pragma unroll
    for (int i = 0; i < 8; i++) { accPV[i][0] = 0ull; accPV[i][1] = 0ull; rs[i] = 0.f; }

    const int krow = tid >> 2;
    const int kc   = (tid & 3) * 16;
    const int swz_t = (tid & 3) << 3;
    const float* Kbase = g_K + (size_t)(bb * S_LEN + krow) * DMODEL + h * HDIM + kc;
    const float* Vbase = g_V + (size_t)(bb * S_LEN + krow) * DMODEL + h * HDIM + kc;

    for (int c0 = 0; c0 < S_LEN; c0 += 64) {
#pragma unroll
        for (int j = 0; j < 4; j++) {
            float4 kv = *(const float4*)(Kbase + (size_t)c0 * DMODEL + j * 4);
            const int e = kc + j * 4;
            Kt[(e + 0) * 64 + (krow ^ swz_t)] = kv.x;
            Kt[(e + 1) * 64 + (krow ^ swz_t)] = kv.y;
            Kt[(e + 2) * 64 + (krow ^ swz_t)] = kv.z;
            Kt[(e + 3) * 64 + (krow ^ swz_t)] = kv.w;
            *(float4*)&Vs[krow * 76 + e] = *(const float4*)(Vbase + (size_t)c0 * DMODEL + j * 4);
        }
        __syncthreads();

        u64 accS[8][2];
#pragma unroll
        for (int i = 0; i < 8; i++) { accS[i][0] = 0ull; accS[i][1] = 0ull; }
#pragma unroll
        for (int k = 0; k < HDIM; k += 2) {
            const int cw = (4 * tx) ^ (((k >> 4) & 3) << 3);
            u64 b00 = *(const u64*)&Kt[k * 64 + cw];
            u64 b01 = *(const u64*)&Kt[k * 64 + cw + 2];
            u64 b10 = *(const u64*)&Kt[(k + 1) * 64 + cw];
            u64 b11 = *(const u64*)&Kt[(k + 1) * 64 + cw + 2];
#pragma unroll
            for (int i = 0; i < 8; i++) {
                float2 aa = *(const float2*)&Qs[(ty * 8 + i) * 68 + k];
                u64 a0 = pack2(aa.x), a1 = pack2(aa.y);
                accS[i][0] = fma2(a0, b00, accS[i][0]);
                accS[i][1] = fma2(a0, b01, accS[i][1]);
                accS[i][0] = fma2(a1, b10, accS[i][0]);
                accS[i][1] = fma2(a1, b11, accS[i][1]);
            }
        }

        const float sc = 0.125f;
#pragma unroll
        for (int i = 0; i < 8; i++) {
            float2 u0 = unpack2(accS[i][0]);
            float2 u1 = unpack2(accS[i][1]);
            float e0 = __expf(u0.x * sc), e1 = __expf(u0.y * sc);
            float e2 = __expf(u1.x * sc), e3 = __expf(u1.y * sc);
            rs[i] += (e0 + e1) + (e2 + e3);
            const int row = ty * 8 + i;
            float4 ev = make_float4(e0, e1, e2, e3);
            *(float4*)&Ss[row * 68 + tx * 4] = ev;
            *(float4*)&attn[((size_t)(p * S_LEN + row0 + row)) * S_LEN + c0 + tx * 4] = ev;
        }
        __syncthreads();

#pragma unroll
        for (int k = 0; k < 64; k += 2) {
            u64 v00 = *(const u64*)&Vs[k * 76 + tx * 4];
            u64 v01 = *(const u64*)&Vs[k * 76 + tx * 4 + 2];
            u64 v10 = *(const u64*)&Vs[(k + 1) * 76 + tx * 4];
            u64 v11 = *(const u64*)&Vs[(k + 1) * 76 + tx * 4 + 2];
#pragma unroll
            for (int i = 0; i < 8; i++) {
                float2 ss = *(const float2*)&Ss[(ty * 8 + i) * 68 + k];
                u64 a0 = pack2(ss.x), a1 = pack2(ss.y);
                accPV[i][0] = fma2(a0, v00, accPV[i][0]);
                accPV[i][1] = fma2(a0, v01, accPV[i][1]);
                accPV[i][0] = fma2(a1, v10, accPV[i][0]);
                accPV[i][1] = fma2(a1, v11, accPV[i][1]);
            }
        }
        __syncthreads();
    }

#pragma unroll
    for (int i = 0; i < 8; i++) {
        float v = rs[i];
        v += __shfl_xor_sync(0xffffffffu, v, 8);
        v += __shfl_xor_sync(0xffffffffu, v, 4);
        v += __shfl_xor_sync(0xffffffffu, v, 2);
        v += __shfl_xor_sync(0xffffffffu, v, 1);
        rs[i] = v;
    }

#pragma unroll
    for (int i = 0; i < 8; i++) {
        const int row = ty * 8 + i;
        const float inv = 1.0f / rs[i];
        if (tx == 0) g_rowinv[p * S_LEN + row0 + row] = inv;
        float2 u0 = unpack2(accPV[i][0]);
        float2 u1 = unpack2(accPV[i][1]);
        float o0 = u0.x * inv, o1 = u0.y * inv, o2 = u1.x * inv, o3 = u1.y * inv;
        __nv_bfloat16 h0 = __float2bfloat16(o0), h1 = __float2bfloat16(o1);
        __nv_bfloat16 h2 = __float2bfloat16(o2), h3 = __float2bfloat16(o3);
        const size_t ci = (size_t)(bb * S_LEN + row0 + row) * DMODEL + h * HDIM + tx * 4;
        *(__nv_bfloat162*)(g_hiC + ci)     = __nv_bfloat162(h0, h1);
        *(__nv_bfloat162*)(g_hiC + ci + 2) = __nv_bfloat162(h2, h3);
        *(__nv_bfloat162*)(g_loC + ci)     = __nv_bfloat162(
            __float2bfloat16(o0 - __bfloat162float(h0)), __float2bfloat16(o1 - __bfloat162float(h1)));
        *(__nv_bfloat162*)(g_loC + ci + 2) = __nv_bfloat162(
            __float2bfloat16(o2 - __bfloat162float(h2)), __float2bfloat16(o3 - __bfloat162float(h3)));
    }
}

// ---------------------------------------------------------------------------
__global__ void __launch_bounds__(256) norm_attn(float* __restrict__ attn)
{
    const size_t i = (size_t)blockIdx.x * 256 + threadIdx.x;
    const size_t r = i >> 9;
    const float inv = g_rowinv[r];
    float4 v = ((const float4*)attn)[i];
    v.x *= inv; v.y *= inv; v.z *= inv; v.w *= inv;
    ((float4*)attn)[i] = v;
}

// ---------------------------------------------------------------------------
extern "C" void kernel_launch(void* const* d_in, const int* in_sizes, int n_in,
                              void* d_out, int out_size) {
    const float* query = (const float*)d_in[0];
    const float* key_  = (const float*)d_in[1];
    const float* value = (const float*)d_in[2];
    const float* Wq = (const float*)d_in[3];
    const float* bq = (const float*)d_in[4];
    const float* Wk = (const float*)d_in[5];
    const float* bk = (const float*)d_in[6];
    const float* Wv = (const float*)d_in[7];
    const float* bv = (const float*)d_in[8];
    const float* Wo = (const float*)d_in[9];
    const float* bo = (const float*)d_in[10];

    float* outp = (float*)d_out;
    float* attn = outp + (size_t)MROWS * DMODEL;   // tuple output: (out, attn)

    static int attr_set = 0;
    if (!attr_set) {
        cudaFuncSetAttribute(qk_pv, cudaFuncAttributeMaxDynamicSharedMemorySize,
                             QKPV_SMEM_FLOATS * (int)sizeof(float));
        attr_set = 1;
    }

    __nv_bfloat16 *hiX, *loX, *hiW, *loW;
    cudaGetSymbolAddress((void**)&hiX, g_hiX);
    cudaGetSymbolAddress((void**)&loX, g_loX);
    cudaGetSymbolAddress((void**)&hiW, g_hiW);
    cudaGetSymbolAddress((void**)&loW, g_loW);

    const int NX = MROWS * DMODEL;       // 4M elems
    const int NW = DMODEL * DMODEL;      // 1M elems
    conv_split<<<NX / 1024, 256>>>(query, hiX, loX);
    conv_split<<<NX / 1024, 256>>>(key_,  hiX + (size_t)NX, loX + (size_t)NX);
    conv_split<<<NX / 1024, 256>>>(value, hiX + (size_t)2 * NX, loX + (size_t)2 * NX);
    conv_split<<<NW / 1024, 256>>>(Wq, hiW, loW);
    conv_split<<<NW / 1024, 256>>>(Wk, hiW + (size_t)NW, loW + (size_t)NW);
    conv_split<<<NW / 1024, 256>>>(Wv, hiW + (size_t)2 * NW, loW + (size_t)2 * NW);
    conv_split<<<NW / 1024, 256>>>(Wo, hiW + (size_t)3 * NW, loW + (size_t)3 * NW);

    qkv_mma<<<dim3(DMODEL / 64, MROWS / 128, 3), 256>>>(bq, bk, bv);
    qk_pv<<<dim3(S_LEN / 128, NPAIRS), 256, QKPV_SMEM_FLOATS * sizeof(float)>>>(attn);
    norm_attn<<<(NPAIRS * (size_t)S_LEN * S_LEN / 4) / 256, 256>>>(attn);
    out_mma<<<dim3(DMODEL / 64, MROWS / 128), 256>>>(bo, outp);
}

// round 6
// speedup vs baseline: 2.4283x; 1.3961x over previous
#include <cuda_runtime.h>
#include <cuda_bf16.h>
#include <cstdint>

#define S_LEN  2048
#define DMODEL 1024
#define NHEAD  16
#define HDIM   64
#define MROWS  4096   // S*B
#define NPAIRS 32     // B*NHEAD
#define NX     ((size_t)MROWS * DMODEL)
#define NW     ((size_t)DMODEL * DMODEL)

// ---------------- scratch globals (allocation-free rule) ----------------
__device__ float g_rowinv[NPAIRS * S_LEN];

__device__ __nv_bfloat16 g_hiX[(size_t)3 * NX];    // converted q/k/v inputs
__device__ __nv_bfloat16 g_loX[(size_t)3 * NX];
__device__ __nv_bfloat16 g_hiW[(size_t)4 * NW];    // converted Wq,Wk,Wv,Wo
__device__ __nv_bfloat16 g_loW[(size_t)4 * NW];
__device__ __nv_bfloat16 g_hiQKV[(size_t)3 * NX];  // projected Q,K,V hi/lo
__device__ __nv_bfloat16 g_loQKV[(size_t)3 * NX];
__device__ __nv_bfloat16 g_hiC[NX];                // attention context hi/lo
__device__ __nv_bfloat16 g_loC[NX];

// ---------------- helpers ----------------
__device__ __forceinline__ uint32_t smem_u32(const void* p) {
    uint32_t a;
    asm("{ .reg .u64 t; cvta.to.shared.u64 t, %1; cvt.u32.u64 %0, t; }" : "=r"(a) : "l"(p));
    return a;
}
__device__ __forceinline__ void ldsm4(uint32_t* r, uint32_t a) {
    asm volatile("ldmatrix.sync.aligned.m8n8.x4.shared.b16 {%0,%1,%2,%3}, [%4];"
        : "=r"(r[0]), "=r"(r[1]), "=r"(r[2]), "=r"(r[3]) : "r"(a));
}
__device__ __forceinline__ void ldsm4t(uint32_t* r, uint32_t a) {
    asm volatile("ldmatrix.sync.aligned.m8n8.x4.trans.shared.b16 {%0,%1,%2,%3}, [%4];"
        : "=r"(r[0]), "=r"(r[1]), "=r"(r[2]), "=r"(r[3]) : "r"(a));
}
__device__ __forceinline__ void mma_bf16(float* d, const uint32_t* a, const uint32_t* b) {
    asm volatile("mma.sync.aligned.m16n8k16.row.col.f32.bf16.bf16.f32 "
        "{%0,%1,%2,%3},{%4,%5,%6,%7},{%8,%9},{%0,%1,%2,%3};"
        : "+f"(d[0]), "+f"(d[1]), "+f"(d[2]), "+f"(d[3])
        : "r"(a[0]), "r"(a[1]), "r"(a[2]), "r"(a[3]), "r"(b[0]), "r"(b[1]));
}
// 64B-row swizzle (GEMM tiles: 4 x 16B chunks per row)
#define SWB(row, ch) (((row) << 6) + ((((ch) ^ (((row) >> 1) & 3))) << 4))
// 128B-row swizzle (attention tiles: 8 x 16B chunks per row)
#define SWB128(row, ch) (((row) << 7) + ((((ch) ^ ((row) & 7))) << 4))

__device__ __forceinline__ void split_pair(float a, float b, uint32_t& hi, uint32_t& lo) {
    __nv_bfloat16 ha = __float2bfloat16(a), hb = __float2bfloat16(b);
    __nv_bfloat162 hp(ha, hb);
    __nv_bfloat162 lp(__float2bfloat16(a - __bfloat162float(ha)),
                      __float2bfloat16(b - __bfloat162float(hb)));
    hi = *(uint32_t*)&hp;
    lo = *(uint32_t*)&lp;
}

// ---------------- fp32 -> bf16 hi/lo split conversion ----------------
__global__ void __launch_bounds__(256) conv_split(
    const float* __restrict__ src, __nv_bfloat16* __restrict__ hi,
    __nv_bfloat16* __restrict__ lo)
{
    const size_t i = ((size_t)blockIdx.x * 256 + threadIdx.x) * 4;
    float4 v = *(const float4*)(src + i);
    uint32_t h01, l01, h23, l23;
    split_pair(v.x, v.y, h01, l01);
    split_pair(v.z, v.w, h23, l23);
    *(uint2*)(hi + i) = make_uint2(h01, h23);
    *(uint2*)(lo + i) = make_uint2(l01, l23);
}

// ---------------------------------------------------------------------------
// mma.sync bf16x3 GEMM: C[128 x 64 per block] = A * W^T + bias
// SPLIT=true: write hi/lo bf16 (QKV path); false: write fp32 (out path).
// ---------------------------------------------------------------------------
template <bool SPLIT>
__device__ __forceinline__ void gemm_mma_core(
    const __nv_bfloat16* __restrict__ Ahi, const __nv_bfloat16* __restrict__ Alo,
    const __nv_bfloat16* __restrict__ Whi, const __nv_bfloat16* __restrict__ Wlo,
    const float* __restrict__ bias, float* __restrict__ Cf,
    __nv_bfloat16* __restrict__ Chi, __nv_bfloat16* __restrict__ Clo)
{
    __shared__ char smbuf[49152];   // 2 x 24576
    const int tid = threadIdx.x, lane = tid & 31, wid = tid >> 5;
    const int warpM = wid & 3, warpN = wid >> 2;
    const int row0 = blockIdx.y * 128, col0 = blockIdx.x * 64;
    const uint32_t sb = smem_u32(smbuf);

    const int grow = tid >> 2, gch = tid & 3;
    const size_t aoff0 = (size_t)(row0 + grow) * (DMODEL * 2) + gch * 16;
    const size_t aoff1 = aoff0 + (size_t)64 * (DMODEL * 2);
    const size_t woff  = (size_t)(col0 + grow) * (DMODEL * 2) + gch * 16;
    const uint32_t dA0 = SWB(grow, gch);
    const uint32_t dA1 = SWB(grow + 64, gch);
    const uint32_t dW  = SWB(grow, gch);

    float acc[2][4][4];
#pragma unroll
    for (int mt = 0; mt < 2; mt++)
#pragma unroll
        for (int nt = 0; nt < 4; nt++)
#pragma unroll
            for (int e = 0; e < 4; e++) acc[mt][nt][e] = 0.f;

    uint4 pre[6];
    pre[0] = *(const uint4*)((const char*)Ahi + aoff0);
    pre[1] = *(const uint4*)((const char*)Ahi + aoff1);
    pre[2] = *(const uint4*)((const char*)Alo + aoff0);
    pre[3] = *(const uint4*)((const char*)Alo + aoff1);
    pre[4] = *(const uint4*)((const char*)Whi + woff);
    pre[5] = *(const uint4*)((const char*)Wlo + woff);

    const int arowl = warpM * 32 + (lane & 7) + ((lane >> 3) & 1) * 8;
    const int achl  = (lane >> 4) & 1;
    const int browl = warpN * 32 + (lane & 7) + ((lane >> 4) & 1) * 8;
    const int bchl  = (lane >> 3) & 1;

    int buf = 0;
    for (int c = 0; c < 32; c++) {
        char* base = smbuf + buf * 24576;
        *(uint4*)(base + 0     + dA0) = pre[0];
        *(uint4*)(base + 0     + dA1) = pre[1];
        *(uint4*)(base + 8192  + dA0) = pre[2];
        *(uint4*)(base + 8192  + dA1) = pre[3];
        *(uint4*)(base + 16384 + dW)  = pre[4];
        *(uint4*)(base + 20480 + dW)  = pre[5];
        __syncthreads();

        if (c + 1 < 32) {
            const size_t cb = (size_t)(c + 1) * 64;
            pre[0] = *(const uint4*)((const char*)Ahi + aoff0 + cb);
            pre[1] = *(const uint4*)((const char*)Ahi + aoff1 + cb);
            pre[2] = *(const uint4*)((const char*)Alo + aoff0 + cb);
            pre[3] = *(const uint4*)((const char*)Alo + aoff1 + cb);
            pre[4] = *(const uint4*)((const char*)Whi + woff + cb);
            pre[5] = *(const uint4*)((const char*)Wlo + woff + cb);
        }

        const uint32_t bb = sb + buf * 24576;
#pragma unroll
        for (int ks = 0; ks < 2; ks++) {
            uint32_t a_hi[2][4], a_lo[2][4], b_hi[2][4], b_lo[2][4];
#pragma unroll
            for (int mt = 0; mt < 2; mt++) {
                const uint32_t ao = SWB(arowl + mt * 16, ks * 2 + achl);
                ldsm4(a_hi[mt], bb + 0    + ao);
                ldsm4(a_lo[mt], bb + 8192 + ao);
            }
#pragma unroll
            for (int np = 0; np < 2; np++) {
                const uint32_t bo = SWB(browl + np * 16, ks * 2 + bchl);
                ldsm4(b_hi[np], bb + 16384 + bo);
                ldsm4(b_lo[np], bb + 20480 + bo);
            }
#pragma unroll
            for (int mt = 0; mt < 2; mt++)
#pragma unroll
                for (int nt = 0; nt < 4; nt++) {
                    const uint32_t* bh = &b_hi[nt >> 1][(nt & 1) * 2];
                    const uint32_t* bl = &b_lo[nt >> 1][(nt & 1) * 2];
                    mma_bf16(acc[mt][nt], a_hi[mt], bh);
                    mma_bf16(acc[mt][nt], a_hi[mt], bl);
                    mma_bf16(acc[mt][nt], a_lo[mt], bh);
                }
        }
        buf ^= 1;
    }

#pragma unroll
    for (int mt = 0; mt < 2; mt++) {
        const int r = row0 + warpM * 32 + mt * 16 + (lane >> 2);
#pragma unroll
        for (int nt = 0; nt < 4; nt++) {
            const int col = col0 + warpN * 32 + nt * 8 + (lane & 3) * 2;
            const float b0 = bias[col], b1 = bias[col + 1];
            const float o0 = acc[mt][nt][0] + b0, o1 = acc[mt][nt][1] + b1;
            const float o2 = acc[mt][nt][2] + b0, o3 = acc[mt][nt][3] + b1;
            if (SPLIT) {
                uint32_t h01, l01, h23, l23;
                split_pair(o0, o1, h01, l01);
                split_pair(o2, o3, h23, l23);
                *(uint32_t*)&Chi[(size_t)r * DMODEL + col]       = h01;
                *(uint32_t*)&Clo[(size_t)r * DMODEL + col]       = l01;
                *(uint32_t*)&Chi[(size_t)(r + 8) * DMODEL + col] = h23;
                *(uint32_t*)&Clo[(size_t)(r + 8) * DMODEL + col] = l23;
            } else {
                *(float2*)&Cf[(size_t)r * DMODEL + col]       = make_float2(o0, o1);
                *(float2*)&Cf[(size_t)(r + 8) * DMODEL + col] = make_float2(o2, o3);
            }
        }
    }
}

__global__ void __launch_bounds__(256, 2) qkv_mma(
    const float* __restrict__ bq, const float* __restrict__ bk, const float* __restrict__ bv)
{
    const int z = blockIdx.z;
    const float* bias = (z == 0) ? bq : (z == 1) ? bk : bv;
    gemm_mma_core<true>(g_hiX + z * NX, g_loX + z * NX,
                        g_hiW + z * NW, g_loW + z * NW, bias,
                        nullptr, g_hiQKV + z * NX, g_loQKV + z * NX);
}

__global__ void __launch_bounds__(256, 2) out_mma(
    const float* __restrict__ bo, float* __restrict__ C)
{
    gemm_mma_core<false>(g_hiC, g_loC, g_hiW + 3 * NW, g_loW + 3 * NW, bo,
                         C, nullptr, nullptr);
}

// ---------------------------------------------------------------------------
// attn_qk: per (pair, 128-row tile) compute expS = exp(QK^T/8) via bf16x3 MMA.
// Writes unnormalized expS to attn; accumulates rowsums -> g_rowinv.
// ---------------------------------------------------------------------------
__global__ void __launch_bounds__(256) attn_qk(float* __restrict__ attn)
{
    __shared__ __align__(16) __nv_bfloat16 Qhi[128 * 64], Qlo[128 * 64];
    __shared__ __align__(16) __nv_bfloat16 Khi[64 * 64],  Klo[64 * 64];
    const int tid = threadIdx.x, lane = tid & 31, wid = tid >> 5;
    const int warpM = wid & 3, warpN = wid >> 2;
    const int p = blockIdx.y, bb = p >> 4, h = p & 15;
    const int row0 = blockIdx.x * 128;
    const uint32_t sQh = smem_u32(Qhi), sQl = smem_u32(Qlo);
    const uint32_t sKh = smem_u32(Khi), sKl = smem_u32(Klo);

    // load Q tile (128 x 64 hd) hi/lo, swizzled
    {
        const int row = tid >> 1, half = tid & 1;
        const size_t ge = (size_t)(bb * S_LEN + row0 + row) * DMODEL + h * HDIM + half * 32;
#pragma unroll
        for (int j = 0; j < 4; j++) {
            const int ch = half * 4 + j;
            const uint32_t so = SWB128(row, ch);
            *(uint4*)((char*)Qhi + so) = *(const uint4*)(g_hiQKV + ge + j * 8);
            *(uint4*)((char*)Qlo + so) = *(const uint4*)(g_loQKV + ge + j * 8);
        }
    }

    float rs[4] = {0.f, 0.f, 0.f, 0.f};   // [mt*2 + rowhalf]
    const int arowl = warpM * 32 + (lane & 7) + ((lane >> 3) & 1) * 8;
    const int achl  = (lane >> 4) & 1;
    const int browl = warpN * 32 + (lane & 7) + ((lane >> 4) & 1) * 8;
    const int bchl  = (lane >> 3) & 1;

    for (int c = 0; c < 32; c++) {
        const int c0 = c * 64;
        __syncthreads();
#pragma unroll
        for (int ps = 0; ps < 2; ps++) {
            const int u = tid + ps * 256;
            const int row = u >> 3, ch = u & 7;
            const size_t ge = NX + (size_t)(bb * S_LEN + c0 + row) * DMODEL + h * HDIM + ch * 8;
            const uint32_t so = SWB128(row, ch);
            *(uint4*)((char*)Khi + so) = *(const uint4*)(g_hiQKV + ge);
            *(uint4*)((char*)Klo + so) = *(const uint4*)(g_loQKV + ge);
        }
        __syncthreads();

        float acc[2][4][4];
#pragma unroll
        for (int mt = 0; mt < 2; mt++)
#pragma unroll
            for (int nt = 0; nt < 4; nt++)
#pragma unroll
                for (int e = 0; e < 4; e++) acc[mt][nt][e] = 0.f;

#pragma unroll
        for (int ks = 0; ks < 4; ks++) {
            uint32_t a_hi[2][4], a_lo[2][4], b_hi[2][4], b_lo[2][4];
#pragma unroll
            for (int mt = 0; mt < 2; mt++) {
                const uint32_t ao = SWB128(arowl + mt * 16, ks * 2 + achl);
                ldsm4(a_hi[mt], sQh + ao);
                ldsm4(a_lo[mt], sQl + ao);
            }
#pragma unroll
            for (int np = 0; np < 2; np++) {
                const uint32_t bo = SWB128(browl + np * 16, ks * 2 + bchl);
                ldsm4(b_hi[np], sKh + bo);
                ldsm4(b_lo[np], sKl + bo);
            }
#pragma unroll
            for (int mt = 0; mt < 2; mt++)
#pragma unroll
                for (int nt = 0; nt < 4; nt++) {
                    const uint32_t* bh = &b_hi[nt >> 1][(nt & 1) * 2];
                    const uint32_t* bl = &b_lo[nt >> 1][(nt & 1) * 2];
                    mma_bf16(acc[mt][nt], a_hi[mt], bh);
                    mma_bf16(acc[mt][nt], a_hi[mt], bl);
                    mma_bf16(acc[mt][nt], a_lo[mt], bh);
                }
        }

        const float sc = 0.125f;
#pragma unroll
        for (int mt = 0; mt < 2; mt++) {
            const int r = row0 + warpM * 32 + mt * 16 + (lane >> 2);
#pragma unroll
            for (int nt = 0; nt < 4; nt++) {
                const int col = c0 + warpN * 32 + nt * 8 + (lane & 3) * 2;
                const float e0 = __expf(acc[mt][nt][0] * sc);
                const float e1 = __expf(acc[mt][nt][1] * sc);
                const float e2 = __expf(acc[mt][nt][2] * sc);
                const float e3 = __expf(acc[mt][nt][3] * sc);
                rs[mt * 2 + 0] += e0 + e1;
                rs[mt * 2 + 1] += e2 + e3;
                const size_t gi = ((size_t)(p * S_LEN) + r) * S_LEN + col;
                *(float2*)&attn[gi]             = make_float2(e0, e1);
                *(float2*)&attn[gi + 8 * S_LEN] = make_float2(e2, e3);
            }
        }
    }

    // rowsum: quad reduce, cross-warp via smem (reuse K buffer)
#pragma unroll
    for (int i = 0; i < 4; i++) {
        rs[i] += __shfl_xor_sync(0xffffffffu, rs[i], 1);
        rs[i] += __shfl_xor_sync(0xffffffffu, rs[i], 2);
    }
    __syncthreads();
    float* rsum = (float*)Khi;
    if (tid < 128) rsum[tid] = 0.f;
    __syncthreads();
    if ((lane & 3) == 0) {
#pragma unroll
        for (int mt = 0; mt < 2; mt++) {
            atomicAdd(&rsum[warpM * 32 + mt * 16 + (lane >> 2)],     rs[mt * 2 + 0]);
            atomicAdd(&rsum[warpM * 32 + mt * 16 + (lane >> 2) + 8], rs[mt * 2 + 1]);
        }
    }
    __syncthreads();
    if (tid < 128) g_rowinv[p * S_LEN + row0 + tid] = 1.0f / rsum[tid];
}

// ---------------------------------------------------------------------------
// attn_pv: reads unnormalized expS, normalizes + writes final attn in-place,
// computes Ctx = attn @ V via bf16x3 MMA (V fragments via ldmatrix.trans).
// ---------------------------------------------------------------------------
__global__ void __launch_bounds__(256) attn_pv(float* __restrict__ attn)
{
    __shared__ __align__(16) __nv_bfloat16 Phi[128 * 64], Plo[128 * 64];
    __shared__ __align__(16) __nv_bfloat16 Vhi[64 * 64],  Vlo[64 * 64];
    const int tid = threadIdx.x, lane = tid & 31, wid = tid >> 5;
    const int warpM = wid & 3, warpN = wid >> 2;
    const int p = blockIdx.y, bb = p >> 4, h = p & 15;
    const int row0 = blockIdx.x * 128;
    const uint32_t sPh = smem_u32(Phi), sPl = smem_u32(Plo);
    const uint32_t sVh = smem_u32(Vhi), sVl = smem_u32(Vlo);

    float rinv[8];
#pragma unroll
    for (int i = 0; i < 8; i++)
        rinv[i] = g_rowinv[p * S_LEN + row0 + (tid >> 4) + i * 16];

    float acc[2][4][4];
#pragma unroll
    for (int mt = 0; mt < 2; mt++)
#pragma unroll
        for (int nt = 0; nt < 4; nt++)
#pragma unroll
            for (int e = 0; e < 4; e++) acc[mt][nt][e] = 0.f;

    const int arowl = warpM * 32 + (lane & 7) + ((lane >> 3) & 1) * 8;
    const int achl  = (lane >> 4) & 1;
    const int vrowl = (lane & 7) + ((lane >> 3) & 1) * 8;   // key within 16-block
    const int vchl  = warpN * 4 + ((lane >> 4) & 1);        // hd 16B-chunk

    for (int c = 0; c < 32; c++) {
        const int c0 = c * 64;
        __syncthreads();
        // V chunk hi/lo
#pragma unroll
        for (int ps = 0; ps < 2; ps++) {
            const int u = tid + ps * 256;
            const int row = u >> 3, ch = u & 7;
            const size_t ge = 2 * NX + (size_t)(bb * S_LEN + c0 + row) * DMODEL + h * HDIM + ch * 8;
            const uint32_t so = SWB128(row, ch);
            *(uint4*)((char*)Vhi + so) = *(const uint4*)(g_hiQKV + ge);
            *(uint4*)((char*)Vlo + so) = *(const uint4*)(g_loQKV + ge);
        }
        // P: load, normalize, write back final attn, split to bf16 hi/lo smem
#pragma unroll
        for (int ps = 0; ps < 8; ps++) {
            const int u = tid + ps * 256;
            const int row = u >> 4, f4 = u & 15;
            const size_t gi = ((size_t)(p * S_LEN) + row0 + row) * S_LEN + c0 + f4 * 4;
            float4 v = *(const float4*)&attn[gi];
            const float inv = rinv[ps];
            v.x *= inv; v.y *= inv; v.z *= inv; v.w *= inv;
            *(float4*)&attn[gi] = v;
            uint32_t h01, l01, h23, l23;
            split_pair(v.x, v.y, h01, l01);
            split_pair(v.z, v.w, h23, l23);
            const uint32_t so = SWB128(row, f4 >> 1) + (f4 & 1) * 8;
            *(uint2*)((char*)Phi + so) = make_uint2(h01, h23);
            *(uint2*)((char*)Plo + so) = make_uint2(l01, l23);
        }
        __syncthreads();

#pragma unroll
        for (int ks = 0; ks < 4; ks++) {
            uint32_t a_hi[2][4], a_lo[2][4], b_hi[2][4], b_lo[2][4];
#pragma unroll
            for (int mt = 0; mt < 2; mt++) {
                const uint32_t ao = SWB128(arowl + mt * 16, ks * 2 + achl);
                ldsm4(a_hi[mt], sPh + ao);
                ldsm4(a_lo[mt], sPl + ao);
            }
#pragma unroll
            for (int np = 0; np < 2; np++) {
                const uint32_t bo = SWB128(ks * 16 + vrowl, vchl + np * 2);
                ldsm4t(b_hi[np], sVh + bo);
                ldsm4t(b_lo[np], sVl + bo);
            }
#pragma unroll
            for (int mt = 0; mt < 2; mt++)
#pragma unroll
                for (int nt = 0; nt < 4; nt++) {
                    const uint32_t* bh = &b_hi[nt >> 1][(nt & 1) * 2];
                    const uint32_t* bl = &b_lo[nt >> 1][(nt & 1) * 2];
                    mma_bf16(acc[mt][nt], a_hi[mt], bh);
                    mma_bf16(acc[mt][nt], a_hi[mt], bl);
                    mma_bf16(acc[mt][nt], a_lo[mt], bh);
                }
        }
    }

    // write context as bf16 hi/lo for out projection
#pragma unroll
    for (int mt = 0; mt < 2; mt++) {
        const int r = bb * S_LEN + row0 + warpM * 32 + mt * 16 + (lane >> 2);
#pragma unroll
        for (int nt = 0; nt < 4; nt++) {
            const int col = h * HDIM + warpN * 32 + nt * 8 + (lane & 3) * 2;
            uint32_t h01, l01, h23, l23;
            split_pair(acc[mt][nt][0], acc[mt][nt][1], h01, l01);
            split_pair(acc[mt][nt][2], acc[mt][nt][3], h23, l23);
            *(uint32_t*)&g_hiC[(size_t)r * DMODEL + col]       = h01;
            *(uint32_t*)&g_loC[(size_t)r * DMODEL + col]       = l01;
            *(uint32_t*)&g_hiC[(size_t)(r + 8) * DMODEL + col] = h23;
            *(uint32_t*)&g_loC[(size_t)(r + 8) * DMODEL + col] = l23;
        }
    }
}

// ---------------------------------------------------------------------------
extern "C" void kernel_launch(void* const* d_in, const int* in_sizes, int n_in,
                              void* d_out, int out_size) {
    const float* query = (const float*)d_in[0];
    const float* key_  = (const float*)d_in[1];
    const float* value = (const float*)d_in[2];
    const float* bq = (const float*)d_in[4];
    const float* bk = (const float*)d_in[6];
    const float* bv = (const float*)d_in[8];
    const float* Wq = (const float*)d_in[3];
    const float* Wk = (const float*)d_in[5];
    const float* Wv = (const float*)d_in[7];
    const float* Wo = (const float*)d_in[9];
    const float* bo = (const float*)d_in[10];

    float* outp = (float*)d_out;
    float* attn = outp + NX;          // tuple output: (out, attn)

    __nv_bfloat16 *hiX, *loX, *hiW, *loW;
    cudaGetSymbolAddress((void**)&hiX, g_hiX);
    cudaGetSymbolAddress((void**)&loX, g_loX);
    cudaGetSymbolAddress((void**)&hiW, g_hiW);
    cudaGetSymbolAddress((void**)&loW, g_loW);

    conv_split<<<NX / 1024, 256>>>(query, hiX, loX);
    conv_split<<<NX / 1024, 256>>>(key_,  hiX + NX, loX + NX);
    conv_split<<<NX / 1024, 256>>>(value, hiX + 2 * NX, loX + 2 * NX);
    conv_split<<<NW / 1024, 256>>>(Wq, hiW, loW);
    conv_split<<<NW / 1024, 256>>>(Wk, hiW + NW, loW + NW);
    conv_split<<<NW / 1024, 256>>>(Wv, hiW + 2 * NW, loW + 2 * NW);
    conv_split<<<NW / 1024, 256>>>(Wo, hiW + 3 * NW, loW + 3 * NW);

    qkv_mma<<<dim3(DMODEL / 64, MROWS / 128, 3), 256>>>(bq, bk, bv);
    attn_qk<<<dim3(S_LEN / 128, NPAIRS), 256>>>(attn);
    attn_pv<<<dim3(S_LEN / 128, NPAIRS), 256>>>(attn);
    out_mma<<<dim3(DMODEL / 64, MROWS / 128), 256>>>(bo, outp);
}

// round 7
// speedup vs baseline: 2.6013x; 1.0712x over previous
#include <cuda_runtime.h>
#include <cuda_bf16.h>
#include <cstdint>

#define S_LEN  2048
#define DMODEL 1024
#define NHEAD  16
#define HDIM   64
#define MROWS  4096   // S*B
#define NPAIRS 32     // B*NHEAD
#define NX     ((size_t)MROWS * DMODEL)
#define NW     ((size_t)DMODEL * DMODEL)

// ---------------- scratch globals (allocation-free rule) ----------------
__device__ __nv_bfloat16 g_hiX[(size_t)3 * NX];    // converted q/k/v inputs
__device__ __nv_bfloat16 g_loX[(size_t)3 * NX];
__device__ __nv_bfloat16 g_hiW[(size_t)4 * NW];    // converted Wq,Wk,Wv,Wo
__device__ __nv_bfloat16 g_loW[(size_t)4 * NW];
__device__ __nv_bfloat16 g_hiQKV[(size_t)3 * NX];  // projected Q,K,V hi/lo
__device__ __nv_bfloat16 g_loQKV[(size_t)3 * NX];
__device__ __nv_bfloat16 g_hiC[NX];                // attention context hi/lo
__device__ __nv_bfloat16 g_loC[NX];

// ---------------- helpers ----------------
__device__ __forceinline__ uint32_t smem_u32(const void* p) {
    uint32_t a;
    asm("{ .reg .u64 t; cvta.to.shared.u64 t, %1; cvt.u32.u64 %0, t; }" : "=r"(a) : "l"(p));
    return a;
}
__device__ __forceinline__ void ldsm4(uint32_t* r, uint32_t a) {
    asm volatile("ldmatrix.sync.aligned.m8n8.x4.shared.b16 {%0,%1,%2,%3}, [%4];"
        : "=r"(r[0]), "=r"(r[1]), "=r"(r[2]), "=r"(r[3]) : "r"(a));
}
__device__ __forceinline__ void ldsm4t(uint32_t* r, uint32_t a) {
    asm volatile("ldmatrix.sync.aligned.m8n8.x4.trans.shared.b16 {%0,%1,%2,%3}, [%4];"
        : "=r"(r[0]), "=r"(r[1]), "=r"(r[2]), "=r"(r[3]) : "r"(a));
}
__device__ __forceinline__ void mma_bf16(float* d, const uint32_t* a, const uint32_t* b) {
    asm volatile("mma.sync.aligned.m16n8k16.row.col.f32.bf16.bf16.f32 "
        "{%0,%1,%2,%3},{%4,%5,%6,%7},{%8,%9},{%0,%1,%2,%3};"
        : "+f"(d[0]), "+f"(d[1]), "+f"(d[2]), "+f"(d[3])
        : "r"(a[0]), "r"(a[1]), "r"(a[2]), "r"(a[3]), "r"(b[0]), "r"(b[1]));
}
// 64B-row swizzle (GEMM tiles)
#define SWB(row, ch) (((row) << 6) + ((((ch) ^ (((row) >> 1) & 3))) << 4))
// 128B-row swizzle (attention tiles)
#define SWB128(row, ch) (((row) << 7) + ((((ch) ^ ((row) & 7))) << 4))

__device__ __forceinline__ void split_pair(float a, float b, uint32_t& hi, uint32_t& lo) {
    __nv_bfloat16 ha = __float2bfloat16(a), hb = __float2bfloat16(b);
    __nv_bfloat162 hp(ha, hb);
    __nv_bfloat162 lp(__float2bfloat16(a - __bfloat162float(ha)),
                      __float2bfloat16(b - __bfloat162float(hb)));
    hi = *(uint32_t*)&hp;
    lo = *(uint32_t*)&lp;
}

// ---------------- fp32 -> bf16 hi/lo split conversion ----------------
__global__ void __launch_bounds__(256) conv_split(
    const float* __restrict__ src, __nv_bfloat16* __restrict__ hi,
    __nv_bfloat16* __restrict__ lo)
{
    const size_t i = ((size_t)blockIdx.x * 256 + threadIdx.x) * 4;
    float4 v = *(const float4*)(src + i);
    uint32_t h01, l01, h23, l23;
    split_pair(v.x, v.y, h01, l01);
    split_pair(v.z, v.w, h23, l23);
    *(uint2*)(hi + i) = make_uint2(h01, h23);
    *(uint2*)(lo + i) = make_uint2(l01, l23);
}

// ---------------------------------------------------------------------------
// mma.sync bf16x3 GEMM (unchanged from R6, passing)
// ---------------------------------------------------------------------------
template <bool SPLIT>
__device__ __forceinline__ void gemm_mma_core(
    const __nv_bfloat16* __restrict__ Ahi, const __nv_bfloat16* __restrict__ Alo,
    const __nv_bfloat16* __restrict__ Whi, const __nv_bfloat16* __restrict__ Wlo,
    const float* __restrict__ bias, float* __restrict__ Cf,
    __nv_bfloat16* __restrict__ Chi, __nv_bfloat16* __restrict__ Clo)
{
    __shared__ char smbuf[49152];   // 2 x 24576
    const int tid = threadIdx.x, lane = tid & 31, wid = tid >> 5;
    const int warpM = wid & 3, warpN = wid >> 2;
    const int row0 = blockIdx.y * 128, col0 = blockIdx.x * 64;
    const uint32_t sb = smem_u32(smbuf);

    const int grow = tid >> 2, gch = tid & 3;
    const size_t aoff0 = (size_t)(row0 + grow) * (DMODEL * 2) + gch * 16;
    const size_t aoff1 = aoff0 + (size_t)64 * (DMODEL * 2);
    const size_t woff  = (size_t)(col0 + grow) * (DMODEL * 2) + gch * 16;
    const uint32_t dA0 = SWB(grow, gch);
    const uint32_t dA1 = SWB(grow + 64, gch);
    const uint32_t dW  = SWB(grow, gch);

    float acc[2][4][4];
#pragma unroll
    for (int mt = 0; mt < 2; mt++)
#pragma unroll
        for (int nt = 0; nt < 4; nt++)
#pragma unroll
            for (int e = 0; e < 4; e++) acc[mt][nt][e] = 0.f;

    uint4 pre[6];
    pre[0] = *(const uint4*)((const char*)Ahi + aoff0);
    pre[1] = *(const uint4*)((const char*)Ahi + aoff1);
    pre[2] = *(const uint4*)((const char*)Alo + aoff0);
    pre[3] = *(const uint4*)((const char*)Alo + aoff1);
    pre[4] = *(const uint4*)((const char*)Whi + woff);
    pre[5] = *(const uint4*)((const char*)Wlo + woff);

    const int arowl = warpM * 32 + (lane & 7) + ((lane >> 3) & 1) * 8;
    const int achl  = (lane >> 4) & 1;
    const int browl = warpN * 32 + (lane & 7) + ((lane >> 4) & 1) * 8;
    const int bchl  = (lane >> 3) & 1;

    int buf = 0;
    for (int c = 0; c < 32; c++) {
        char* base = smbuf + buf * 24576;
        *(uint4*)(base + 0     + dA0) = pre[0];
        *(uint4*)(base + 0     + dA1) = pre[1];
        *(uint4*)(base + 8192  + dA0) = pre[2];
        *(uint4*)(base + 8192  + dA1) = pre[3];
        *(uint4*)(base + 16384 + dW)  = pre[4];
        *(uint4*)(base + 20480 + dW)  = pre[5];
        __syncthreads();

        if (c + 1 < 32) {
            const size_t cb = (size_t)(c + 1) * 64;
            pre[0] = *(const uint4*)((const char*)Ahi + aoff0 + cb);
            pre[1] = *(const uint4*)((const char*)Ahi + aoff1 + cb);
            pre[2] = *(const uint4*)((const char*)Alo + aoff0 + cb);
            pre[3] = *(const uint4*)((const char*)Alo + aoff1 + cb);
            pre[4] = *(const uint4*)((const char*)Whi + woff + cb);
            pre[5] = *(const uint4*)((const char*)Wlo + woff + cb);
        }

        const uint32_t bb = sb + buf * 24576;
#pragma unroll
        for (int ks = 0; ks < 2; ks++) {
            uint32_t a_hi[2][4], a_lo[2][4], b_hi[2][4], b_lo[2][4];
#pragma unroll
            for (int mt = 0; mt < 2; mt++) {
                const uint32_t ao = SWB(arowl + mt * 16, ks * 2 + achl);
                ldsm4(a_hi[mt], bb + 0    + ao);
                ldsm4(a_lo[mt], bb + 8192 + ao);
            }
#pragma unroll
            for (int np = 0; np < 2; np++) {
                const uint32_t bo = SWB(browl + np * 16, ks * 2 + bchl);
                ldsm4(b_hi[np], bb + 16384 + bo);
                ldsm4(b_lo[np], bb + 20480 + bo);
            }
#pragma unroll
            for (int mt = 0; mt < 2; mt++)
#pragma unroll
                for (int nt = 0; nt < 4; nt++) {
                    const uint32_t* bh = &b_hi[nt >> 1][(nt & 1) * 2];
                    const uint32_t* bl = &b_lo[nt >> 1][(nt & 1) * 2];
                    mma_bf16(acc[mt][nt], a_hi[mt], bh);
                    mma_bf16(acc[mt][nt], a_hi[mt], bl);
                    mma_bf16(acc[mt][nt], a_lo[mt], bh);
                }
        }
        buf ^= 1;
    }

#pragma unroll
    for (int mt = 0; mt < 2; mt++) {
        const int r = row0 + warpM * 32 + mt * 16 + (lane >> 2);
#pragma unroll
        for (int nt = 0; nt < 4; nt++) {
            const int col = col0 + warpN * 32 + nt * 8 + (lane & 3) * 2;
            const float b0 = bias[col], b1 = bias[col + 1];
            const float o0 = acc[mt][nt][0] + b0, o1 = acc[mt][nt][1] + b1;
            const float o2 = acc[mt][nt][2] + b0, o3 = acc[mt][nt][3] + b1;
            if (SPLIT) {
                uint32_t h01, l01, h23, l23;
                split_pair(o0, o1, h01, l01);
                split_pair(o2, o3, h23, l23);
                *(uint32_t*)&Chi[(size_t)r * DMODEL + col]       = h01;
                *(uint32_t*)&Clo[(size_t)r * DMODEL + col]       = l01;
                *(uint32_t*)&Chi[(size_t)(r + 8) * DMODEL + col] = h23;
                *(uint32_t*)&Clo[(size_t)(r + 8) * DMODEL + col] = l23;
            } else {
                *(float2*)&Cf[(size_t)r * DMODEL + col]       = make_float2(o0, o1);
                *(float2*)&Cf[(size_t)(r + 8) * DMODEL + col] = make_float2(o2, o3);
            }
        }
    }
}

__global__ void __launch_bounds__(256, 2) qkv_mma(
    const float* __restrict__ bq, const float* __restrict__ bk, const float* __restrict__ bv)
{
    const int z = blockIdx.z;
    const float* bias = (z == 0) ? bq : (z == 1) ? bk : bv;
    gemm_mma_core<true>(g_hiX + z * NX, g_loX + z * NX,
                        g_hiW + z * NW, g_loW + z * NW, bias,
                        nullptr, g_hiQKV + z * NX, g_loQKV + z * NX);
}

__global__ void __launch_bounds__(256, 2) out_mma(
    const float* __restrict__ bo, float* __restrict__ C)
{
    gemm_mma_core<false>(g_hiC, g_loC, g_hiW + 3 * NW, g_loW + 3 * NW, bo,
                         C, nullptr, nullptr);
}

// ---------------------------------------------------------------------------
// Fused flash attention: two passes over K per (pair, 128-row) tile.
// Pass 1: hi-only QK^T -> exp -> rowsums (no stores).
// Pass 2: bf16x3 QK^T -> exp*rowinv -> write final attn once -> P to bf16
//         hi/lo in registers -> PV bf16x3 -> ctx (hi/lo bf16).
// Dyn smem: Qhi 16K | Qlo 16K | Khi 8K | Klo 8K | Vhi 8K | Vlo 8K | rsum 512
// ---------------------------------------------------------------------------
#define ATT_SMEM (65536 + 512)

__global__ void __launch_bounds__(256) attn_fused(float* __restrict__ attn)
{
    extern __shared__ char sm[];
    const uint32_t sQh = smem_u32(sm);
    const uint32_t sQl = sQh + 16384;
    const uint32_t sKh = sQh + 32768;
    const uint32_t sKl = sQh + 40960;
    const uint32_t sVh = sQh + 49152;
    const uint32_t sVl = sQh + 57344;
    float* rsum = (float*)(sm + 65536);

    const int tid = threadIdx.x, lane = tid & 31, wid = tid >> 5;
    const int warpM = wid & 3, warpN = wid >> 2;
    const int p = blockIdx.y, bb = p >> 4, h = p & 15;
    const int row0 = blockIdx.x * 128;

    // load Q tile 128 x 64 hi/lo
#pragma unroll
    for (int ps = 0; ps < 4; ps++) {
        const int u = tid + ps * 256;
        const int row = u >> 3, ch = u & 7;
        const size_t ge = (size_t)(bb * S_LEN + row0 + row) * DMODEL + h * HDIM + ch * 8;
        const uint32_t so = SWB128(row, ch);
        *(uint4*)(sm + (sQh - smem_u32(sm)) + so) = *(const uint4*)(g_hiQKV + ge);
        *(uint4*)(sm + (sQl - smem_u32(sm)) + so) = *(const uint4*)(g_loQKV + ge);
    }
    if (tid < 128) rsum[tid] = 0.f;

    const int arowl = warpM * 32 + (lane & 7) + ((lane >> 3) & 1) * 8;
    const int achl  = (lane >> 4) & 1;
    const int browl = warpN * 32 + (lane & 7) + ((lane >> 4) & 1) * 8;
    const int bchl  = (lane >> 3) & 1;
    const int vrowl = (lane & 7) + ((lane >> 3) & 1) * 8;
    const int vtog  = (lane >> 4) & 1;
    const float sc = 0.125f;

    // ---------------- pass 1: rowsums (hi-only) ----------------
    float rs[4] = {0.f, 0.f, 0.f, 0.f};
    for (int c = 0; c < 32; c++) {
        const int c0 = c * 64;
        __syncthreads();
#pragma unroll
        for (int ps = 0; ps < 2; ps++) {
            const int u = tid + ps * 256;
            const int row = u >> 3, ch = u & 7;
            const size_t ge = NX + (size_t)(bb * S_LEN + c0 + row) * DMODEL + h * HDIM + ch * 8;
            *(uint4*)(sm + 32768 + SWB128(row, ch)) = *(const uint4*)(g_hiQKV + ge);
        }
        __syncthreads();

        float acc[2][4][4];
#pragma unroll
        for (int mt = 0; mt < 2; mt++)
#pragma unroll
            for (int nt = 0; nt < 4; nt++)
#pragma unroll
                for (int e = 0; e < 4; e++) acc[mt][nt][e] = 0.f;
#pragma unroll
        for (int ks = 0; ks < 4; ks++) {
            uint32_t a_hi[2][4], b_hi[2][4];
#pragma unroll
            for (int mt = 0; mt < 2; mt++)
                ldsm4(a_hi[mt], sQh + SWB128(arowl + mt * 16, ks * 2 + achl));
#pragma unroll
            for (int np = 0; np < 2; np++)
                ldsm4(b_hi[np], sKh + SWB128(browl + np * 16, ks * 2 + bchl));
#pragma unroll
            for (int mt = 0; mt < 2; mt++)
#pragma unroll
                for (int nt = 0; nt < 4; nt++)
                    mma_bf16(acc[mt][nt], a_hi[mt], &b_hi[nt >> 1][(nt & 1) * 2]);
        }
#pragma unroll
        for (int mt = 0; mt < 2; mt++)
#pragma unroll
            for (int nt = 0; nt < 4; nt++) {
                rs[mt * 2 + 0] += __expf(acc[mt][nt][0] * sc) + __expf(acc[mt][nt][1] * sc);
                rs[mt * 2 + 1] += __expf(acc[mt][nt][2] * sc) + __expf(acc[mt][nt][3] * sc);
            }
    }
#pragma unroll
    for (int i = 0; i < 4; i++) {
        rs[i] += __shfl_xor_sync(0xffffffffu, rs[i], 1);
        rs[i] += __shfl_xor_sync(0xffffffffu, rs[i], 2);
    }
    if ((lane & 3) == 0) {
#pragma unroll
        for (int mt = 0; mt < 2; mt++) {
            atomicAdd(&rsum[warpM * 32 + mt * 16 + (lane >> 2)],     rs[mt * 2 + 0]);
            atomicAdd(&rsum[warpM * 32 + mt * 16 + (lane >> 2) + 8], rs[mt * 2 + 1]);
        }
    }
    __syncthreads();
    if (tid < 128) rsum[tid] = 1.0f / rsum[tid];
    __syncthreads();
    float rinv[2][2];
#pragma unroll
    for (int mt = 0; mt < 2; mt++) {
        rinv[mt][0] = rsum[warpM * 32 + mt * 16 + (lane >> 2)];
        rinv[mt][1] = rsum[warpM * 32 + mt * 16 + (lane >> 2) + 8];
    }

    // ---------------- pass 2: attn write + PV ----------------
    float ctx[2][8][4];
#pragma unroll
    for (int mt = 0; mt < 2; mt++)
#pragma unroll
        for (int nt = 0; nt < 8; nt++)
#pragma unroll
            for (int e = 0; e < 4; e++) ctx[mt][nt][e] = 0.f;

    for (int c = 0; c < 32; c++) {
        const int c0 = c * 64;
        __syncthreads();
#pragma unroll
        for (int ps = 0; ps < 2; ps++) {
            const int u = tid + ps * 256;
            const int row = u >> 3, ch = u & 7;
            const uint32_t so = SWB128(row, ch);
            const size_t geK = NX     + (size_t)(bb * S_LEN + c0 + row) * DMODEL + h * HDIM + ch * 8;
            const size_t geV = 2 * NX + (size_t)(bb * S_LEN + c0 + row) * DMODEL + h * HDIM + ch * 8;
            *(uint4*)(sm + 32768 + so) = *(const uint4*)(g_hiQKV + geK);
            *(uint4*)(sm + 40960 + so) = *(const uint4*)(g_loQKV + geK);
            *(uint4*)(sm + 49152 + so) = *(const uint4*)(g_hiQKV + geV);
            *(uint4*)(sm + 57344 + so) = *(const uint4*)(g_loQKV + geV);
        }
        __syncthreads();

        float acc[2][4][4];
#pragma unroll
        for (int mt = 0; mt < 2; mt++)
#pragma unroll
            for (int nt = 0; nt < 4; nt++)
#pragma unroll
                for (int e = 0; e < 4; e++) acc[mt][nt][e] = 0.f;
#pragma unroll
        for (int ks = 0; ks < 4; ks++) {
            uint32_t a_hi[2][4], a_lo[2][4], b_hi[2][4], b_lo[2][4];
#pragma unroll
            for (int mt = 0; mt < 2; mt++) {
                const uint32_t ao = SWB128(arowl + mt * 16, ks * 2 + achl);
                ldsm4(a_hi[mt], sQh + ao);
                ldsm4(a_lo[mt], sQl + ao);
            }
#pragma unroll
            for (int np = 0; np < 2; np++) {
                const uint32_t bo = SWB128(browl + np * 16, ks * 2 + bchl);
                ldsm4(b_hi[np], sKh + bo);
                ldsm4(b_lo[np], sKl + bo);
            }
#pragma unroll
            for (int mt = 0; mt < 2; mt++)
#pragma unroll
                for (int nt = 0; nt < 4; nt++) {
                    const uint32_t* bh = &b_hi[nt >> 1][(nt & 1) * 2];
                    const uint32_t* bl = &b_lo[nt >> 1][(nt & 1) * 2];
                    mma_bf16(acc[mt][nt], a_hi[mt], bh);
                    mma_bf16(acc[mt][nt], a_hi[mt], bl);
                    mma_bf16(acc[mt][nt], a_lo[mt], bh);
                }
        }

        // normalize, write final attn, keep P in acc
#pragma unroll
        for (int mt = 0; mt < 2; mt++) {
            const int r = row0 + warpM * 32 + mt * 16 + (lane >> 2);
#pragma unroll
            for (int nt = 0; nt < 4; nt++) {
                const int col = c0 + warpN * 32 + nt * 8 + (lane & 3) * 2;
                const float p0 = __expf(acc[mt][nt][0] * sc) * rinv[mt][0];
                const float p1 = __expf(acc[mt][nt][1] * sc) * rinv[mt][0];
                const float p2 = __expf(acc[mt][nt][2] * sc) * rinv[mt][1];
                const float p3 = __expf(acc[mt][nt][3] * sc) * rinv[mt][1];
                const size_t gi = ((size_t)(p * S_LEN) + r) * S_LEN + col;
                *(float2*)&attn[gi]             = make_float2(p0, p1);
                *(float2*)&attn[gi + 8 * S_LEN] = make_float2(p2, p3);
                acc[mt][nt][0] = p0; acc[mt][nt][1] = p1;
                acc[mt][nt][2] = p2; acc[mt][nt][3] = p3;
            }
        }

        // PV: this warp handles its 32 keys (2 groups of 16), full hd=64
#pragma unroll
        for (int kg = 0; kg < 2; kg++) {
            uint32_t ah[2][4], al[2][4];
#pragma unroll
            for (int mt = 0; mt < 2; mt++) {
                split_pair(acc[mt][2 * kg][0],     acc[mt][2 * kg][1],     ah[mt][0], al[mt][0]);
                split_pair(acc[mt][2 * kg][2],     acc[mt][2 * kg][3],     ah[mt][1], al[mt][1]);
                split_pair(acc[mt][2 * kg + 1][0], acc[mt][2 * kg + 1][1], ah[mt][2], al[mt][2]);
                split_pair(acc[mt][2 * kg + 1][2], acc[mt][2 * kg + 1][3], ah[mt][3], al[mt][3]);
            }
            uint32_t bh[4][4], bl[4][4];
            const int kb = warpN * 32 + kg * 16;
#pragma unroll
            for (int ld = 0; ld < 4; ld++) {
                const uint32_t bo = SWB128(kb + vrowl, ld * 2 + vtog);
                ldsm4t(bh[ld], sVh + bo);
                ldsm4t(bl[ld], sVl + bo);
            }
#pragma unroll
            for (int mt = 0; mt < 2; mt++)
#pragma unroll
                for (int nt = 0; nt < 8; nt++) {
                    const uint32_t* bhp = &bh[nt >> 1][(nt & 1) * 2];
                    const uint32_t* blp = &bl[nt >> 1][(nt & 1) * 2];
                    mma_bf16(ctx[mt][nt], ah[mt], bhp);
                    mma_bf16(ctx[mt][nt], ah[mt], blp);
                    mma_bf16(ctx[mt][nt], al[mt], bhp);
                }
        }
    }

    // cross-warpN ctx reduction via smem (reuse Q region: 128x64 fp32 = 32KB)
    __syncthreads();
    float* red = (float*)sm;
    if (warpN == 1) {
#pragma unroll
        for (int mt = 0; mt < 2; mt++) {
            const int rl = warpM * 32 + mt * 16 + (lane >> 2);
#pragma unroll
            for (int nt = 0; nt < 8; nt++) {
                const int col = nt * 8 + (lane & 3) * 2;
                *(float2*)&red[rl * 64 + col]       = make_float2(ctx[mt][nt][0], ctx[mt][nt][1]);
                *(float2*)&red[(rl + 8) * 64 + col] = make_float2(ctx[mt][nt][2], ctx[mt][nt][3]);
            }
        }
    }
    __syncthreads();
    if (warpN == 0) {
#pragma unroll
        for (int mt = 0; mt < 2; mt++) {
            const int rl = warpM * 32 + mt * 16 + (lane >> 2);
            const size_t gr0 = (size_t)(bb * S_LEN + row0 + rl) * DMODEL + h * HDIM;
            const size_t gr1 = gr0 + (size_t)8 * DMODEL;
#pragma unroll
            for (int nt = 0; nt < 8; nt++) {
                const int col = nt * 8 + (lane & 3) * 2;
                float2 s0 = *(float2*)&red[rl * 64 + col];
                float2 s1 = *(float2*)&red[(rl + 8) * 64 + col];
                const float o0 = ctx[mt][nt][0] + s0.x, o1 = ctx[mt][nt][1] + s0.y;
                const float o2 = ctx[mt][nt][2] + s1.x, o3 = ctx[mt][nt][3] + s1.y;
                uint32_t h01, l01, h23, l23;
                split_pair(o0, o1, h01, l01);
                split_pair(o2, o3, h23, l23);
                *(uint32_t*)&g_hiC[gr0 + col] = h01;
                *(uint32_t*)&g_loC[gr0 + col] = l01;
                *(uint32_t*)&g_hiC[gr1 + col] = h23;
                *(uint32_t*)&g_loC[gr1 + col] = l23;
            }
        }
    }
}

// ---------------------------------------------------------------------------
extern "C" void kernel_launch(void* const* d_in, const int* in_sizes, int n_in,
                              void* d_out, int out_size) {
    const float* query = (const float*)d_in[0];
    const float* key_  = (const float*)d_in[1];
    const float* value = (const float*)d_in[2];
    const float* Wq = (const float*)d_in[3];
    const float* bq = (const float*)d_in[4];
    const float* Wk = (const float*)d_in[5];
    const float* bk = (const float*)d_in[6];
    const float* Wv = (const float*)d_in[7];
    const float* bv = (const float*)d_in[8];
    const float* Wo = (const float*)d_in[9];
    const float* bo = (const float*)d_in[10];

    float* outp = (float*)d_out;
    float* attn = outp + NX;          // tuple output: (out, attn)

    static int attr_set = 0;
    if (!attr_set) {
        cudaFuncSetAttribute(attn_fused, cudaFuncAttributeMaxDynamicSharedMemorySize, ATT_SMEM);
        attr_set = 1;
    }

    __nv_bfloat16 *hiX, *loX, *hiW, *loW;
    cudaGetSymbolAddress((void**)&hiX, g_hiX);
    cudaGetSymbolAddress((void**)&loX, g_loX);
    cudaGetSymbolAddress((void**)&hiW, g_hiW);
    cudaGetSymbolAddress((void**)&loW, g_loW);

    conv_split<<<NX / 1024, 256>>>(query, hiX, loX);
    conv_split<<<NX / 1024, 256>>>(key_,  hiX + NX, loX + NX);
    conv_split<<<NX / 1024, 256>>>(value, hiX + 2 * NX, loX + 2 * NX);
    conv_split<<<NW / 1024, 256>>>(Wq, hiW, loW);
    conv_split<<<NW / 1024, 256>>>(Wk, hiW + NW, loW + NW);
    conv_split<<<NW / 1024, 256>>>(Wv, hiW + 2 * NW, loW + 2 * NW);
    conv_split<<<NW / 1024, 256>>>(Wo, hiW + 3 * NW, loW + 3 * NW);

    qkv_mma<<<dim3(DMODEL / 64, MROWS / 128, 3), 256>>>(bq, bk, bv);
    attn_fused<<<dim3(S_LEN / 128, NPAIRS), 256, ATT_SMEM>>>(attn);
    out_mma<<<dim3(DMODEL / 64, MROWS / 128), 256>>>(bo, outp);
}